// round 3
// baseline (speedup 1.0000x reference)
#include <cuda_runtime.h>
#include <math.h>

#define BB 4
#define SS 2048
#define EE 1024
#define HH 16
#define DH 64
#define MM (BB*SS)        // 8192
#define SMLD 68           // smem row pitch (floats), pad for bank conflicts

// Scratch (allocation-free rule: __device__ globals)
__device__ float g_q[(size_t)BB*HH*SS*DH];  // transposed per plane: [b*H+h][d][s], pre-scaled by 1/8
__device__ float g_k[(size_t)BB*HH*SS*DH];  // transposed per plane: [b*H+h][d][s]
__device__ float g_v[(size_t)BB*HH*SS*DH];  // natural: [b*H+h][s][d]
__device__ float g_z[(size_t)BB*SS*HH*DH];  // [b][s][h*64+d]

// ---------------------------------------------------------------------------
// Kernel 1: QKV projections. grid (MM/64, 3*H), block 256.
// Per head: C[8192,64] = x[8192,1024] @ W[h][1024,64] + bias
// q,k written transposed ([bh][d][s]); v natural. q scaled by 0.125.
// ---------------------------------------------------------------------------
__global__ __launch_bounds__(256) void qkv_kernel(
    const float* __restrict__ x,
    const float* __restrict__ Wq, const float* __restrict__ bq,
    const float* __restrict__ Wk, const float* __restrict__ bk,
    const float* __restrict__ Wv, const float* __restrict__ bv)
{
    __shared__ float As[16][SMLD];  // As[k][m]
    __shared__ float Bs[16][SMLD];  // Bs[k][n]

    const int m0  = blockIdx.x * 64;
    const int h   = blockIdx.y & (HH - 1);
    const int mat = blockIdx.y >> 4;      // 0=q, 1=k, 2=v

    const float* W;
    const float* bias;
    if (mat == 0)      { W = Wq + (size_t)h * EE * DH; bias = bq + h * DH; }
    else if (mat == 1) { W = Wk + (size_t)h * EE * DH; bias = bk + h * DH; }
    else               { W = Wv + (size_t)h * EE * DH; bias = bv + h * DH; }

    const int tid = threadIdx.x;
    const int tx = tid & 15, ty = tid >> 4;
    const int arow = tid >> 2, akq = tid & 3;   // A loader: 64 rows x 4 float4
    const int bkk  = tid >> 4, bcq = tid & 15;  // B loader: 16 rows x 16 float4

    float acc[4][4] = {};

    for (int k0 = 0; k0 < EE; k0 += 16) {
        float4 av  = *(const float4*)(x + (size_t)(m0 + arow) * EE + k0 + 4 * akq);
        float4 bv4 = *(const float4*)(W + (size_t)(k0 + bkk) * DH + 4 * bcq);
        As[4*akq+0][arow] = av.x; As[4*akq+1][arow] = av.y;
        As[4*akq+2][arow] = av.z; As[4*akq+3][arow] = av.w;
        *(float4*)&Bs[bkk][4*bcq] = bv4;
        __syncthreads();
        #pragma unroll
        for (int kk = 0; kk < 16; kk++) {
            float a[4];
            #pragma unroll
            for (int i = 0; i < 4; i++) a[i] = As[kk][4*ty + i];
            float4 b4 = *(const float4*)&Bs[kk][4*tx];
            float b[4] = {b4.x, b4.y, b4.z, b4.w};
            #pragma unroll
            for (int i = 0; i < 4; i++)
                #pragma unroll
                for (int j = 0; j < 4; j++)
                    acc[i][j] = fmaf(a[i], b[j], acc[i][j]);
        }
        __syncthreads();
    }

    float bvals[4];
    #pragma unroll
    for (int j = 0; j < 4; j++) bvals[j] = bias[4*tx + j];

    #pragma unroll
    for (int i = 0; i < 4; i++) {
        int m  = m0 + 4*ty + i;
        int bb = m >> 11;          // / 2048
        int s  = m & (SS - 1);
        if (mat == 2) {
            float* orow = g_v + ((size_t)(bb*HH + h) * SS + s) * DH + 4*tx;
            *(float4*)orow = make_float4(acc[i][0] + bvals[0], acc[i][1] + bvals[1],
                                         acc[i][2] + bvals[2], acc[i][3] + bvals[3]);
        } else {
            float scale = (mat == 0) ? 0.125f : 1.0f;   // 1/sqrt(64) folded into q
            float* plane = ((mat == 0) ? g_q : g_k) + (size_t)(bb*HH + h) * DH * SS;
            #pragma unroll
            for (int j = 0; j < 4; j++)
                plane[(size_t)(4*tx + j) * SS + s] = (acc[i][j] + bvals[j]) * scale;
        }
    }
}

// ---------------------------------------------------------------------------
// Kernel 2: flash attention. grid (SS/64, B*H), block 256, dyn smem 3*64*SMLD*4.
// Online-softmax over 32 key tiles of 64; writes z in [B,S,H*Dh] layout.
// ---------------------------------------------------------------------------
__global__ __launch_bounds__(256) void attn_kernel()
{
    extern __shared__ float sm[];
    float* Qs = sm;                 // [64][SMLD] : Qs[d][i]
    float* Ks = sm + 64 * SMLD;     // [64][SMLD] : Ks[d][j]; reused as Ps[t][i]
    float* Vs = sm + 2 * 64 * SMLD; // [64][SMLD] : Vs[t][c]

    const int s0  = blockIdx.x * 64;
    const int bh  = blockIdx.y;
    const int tid = threadIdx.x;
    const int tx = tid & 15, ty = tid >> 4;

    const float* qp = g_q + (size_t)bh * DH * SS;
    const float* kp = g_k + (size_t)bh * DH * SS;
    const float* vp = g_v + (size_t)bh * SS * DH;

    // Load Q tile (already transposed + scaled in gmem)
    #pragma unroll
    for (int r = 0; r < 4; r++) {
        int lin = tid + r * 256;
        int d = lin >> 4, sq = lin & 15;
        *(float4*)&Qs[d * SMLD + 4*sq] = *(const float4*)(qp + (size_t)d * SS + s0 + 4*sq);
    }

    float m_r[4], l_r[4], o[4][4];
    #pragma unroll
    for (int i = 0; i < 4; i++) {
        m_r[i] = -1e30f; l_r[i] = 0.f;
        #pragma unroll
        for (int j = 0; j < 4; j++) o[i][j] = 0.f;
    }

    for (int t0 = 0; t0 < SS; t0 += 64) {
        // Load K (transposed gmem -> direct copy) and V (natural)
        #pragma unroll
        for (int r = 0; r < 4; r++) {
            int lin = tid + r * 256;
            int a = lin >> 4, q4 = lin & 15;
            *(float4*)&Ks[a * SMLD + 4*q4] = *(const float4*)(kp + (size_t)a * SS + t0 + 4*q4);
            *(float4*)&Vs[a * SMLD + 4*q4] = *(const float4*)(vp + (size_t)(t0 + a) * DH + 4*q4);
        }
        __syncthreads();

        // S = Q K^T (outer products over d)
        float sreg[4][4] = {};
        #pragma unroll 16
        for (int d = 0; d < 64; d++) {
            float a[4];
            #pragma unroll
            for (int i = 0; i < 4; i++) a[i] = Qs[d * SMLD + 4*ty + i];
            float4 b4 = *(const float4*)&Ks[d * SMLD + 4*tx];
            float b[4] = {b4.x, b4.y, b4.z, b4.w};
            #pragma unroll
            for (int i = 0; i < 4; i++)
                #pragma unroll
                for (int j = 0; j < 4; j++)
                    sreg[i][j] = fmaf(a[i], b[j], sreg[i][j]);
        }

        // Online softmax (rows split across the 16 tx lanes)
        #pragma unroll
        for (int i = 0; i < 4; i++) {
            float rm = fmaxf(fmaxf(sreg[i][0], sreg[i][1]), fmaxf(sreg[i][2], sreg[i][3]));
            #pragma unroll
            for (int msk = 8; msk >= 1; msk >>= 1)
                rm = fmaxf(rm, __shfl_xor_sync(0xffffffffu, rm, msk));
            float mnew  = fmaxf(m_r[i], rm);
            float alpha = __expf(m_r[i] - mnew);
            m_r[i] = mnew;
            float rs = 0.f;
            #pragma unroll
            for (int j = 0; j < 4; j++) {
                float p = __expf(sreg[i][j] - mnew);
                sreg[i][j] = p; rs += p;
            }
            #pragma unroll
            for (int msk = 8; msk >= 1; msk >>= 1)
                rs += __shfl_xor_sync(0xffffffffu, rs, msk);
            l_r[i] = l_r[i] * alpha + rs;
            #pragma unroll
            for (int j = 0; j < 4; j++) o[i][j] *= alpha;
        }
        __syncthreads();   // all done reading Ks

        // P^T into the K buffer: Ps[t][i]
        #pragma unroll
        for (int j = 0; j < 4; j++)
            #pragma unroll
            for (int i = 0; i < 4; i++)
                Ks[(4*tx + j) * SMLD + 4*ty + i] = sreg[i][j];
        __syncthreads();

        // O += P V (outer products over t)
        #pragma unroll 16
        for (int t = 0; t < 64; t++) {
            float a[4];
            #pragma unroll
            for (int i = 0; i < 4; i++) a[i] = Ks[t * SMLD + 4*ty + i];
            float4 b4 = *(const float4*)&Vs[t * SMLD + 4*tx];
            float b[4] = {b4.x, b4.y, b4.z, b4.w};
            #pragma unroll
            for (int i = 0; i < 4; i++)
                #pragma unroll
                for (int j = 0; j < 4; j++)
                    o[i][j] = fmaf(a[i], b[j], o[i][j]);
        }
        __syncthreads();
    }

    const int bb = bh >> 4, h = bh & 15;
    #pragma unroll
    for (int i = 0; i < 4; i++) {
        float inv = 1.0f / l_r[i];
        float* zrow = g_z + ((size_t)bb * SS + s0 + 4*ty + i) * (HH*DH) + h * DH + 4*tx;
        *(float4*)zrow = make_float4(o[i][0]*inv, o[i][1]*inv, o[i][2]*inv, o[i][3]*inv);
    }
}

// ---------------------------------------------------------------------------
// Kernel 3: output projection. grid (MM/64, EE/64), block 256.
// out[8192,1024] = g_z[8192,1024] @ Wo[1024,1024] + bo
// ---------------------------------------------------------------------------
__global__ __launch_bounds__(256) void oproj_kernel(
    const float* __restrict__ Wo, const float* __restrict__ bo,
    float* __restrict__ out)
{
    __shared__ float As[16][SMLD];
    __shared__ float Bs[16][SMLD];

    const int m0 = blockIdx.x * 64;
    const int n0 = blockIdx.y * 64;
    const int tid = threadIdx.x;
    const int tx = tid & 15, ty = tid >> 4;
    const int arow = tid >> 2, akq = tid & 3;
    const int bkk  = tid >> 4, bcq = tid & 15;

    float acc[4][4] = {};

    for (int k0 = 0; k0 < HH*DH; k0 += 16) {
        float4 av  = *(const float4*)(g_z + (size_t)(m0 + arow) * (HH*DH) + k0 + 4*akq);
        float4 bv4 = *(const float4*)(Wo + (size_t)(k0 + bkk) * EE + n0 + 4*bcq);
        As[4*akq+0][arow] = av.x; As[4*akq+1][arow] = av.y;
        As[4*akq+2][arow] = av.z; As[4*akq+3][arow] = av.w;
        *(float4*)&Bs[bkk][4*bcq] = bv4;
        __syncthreads();
        #pragma unroll
        for (int kk = 0; kk < 16; kk++) {
            float a[4];
            #pragma unroll
            for (int i = 0; i < 4; i++) a[i] = As[kk][4*ty + i];
            float4 b4 = *(const float4*)&Bs[kk][4*tx];
            float b[4] = {b4.x, b4.y, b4.z, b4.w};
            #pragma unroll
            for (int i = 0; i < 4; i++)
                #pragma unroll
                for (int j = 0; j < 4; j++)
                    acc[i][j] = fmaf(a[i], b[j], acc[i][j]);
        }
        __syncthreads();
    }

    float bvals[4];
    #pragma unroll
    for (int j = 0; j < 4; j++) bvals[j] = bo[n0 + 4*tx + j];

    #pragma unroll
    for (int i = 0; i < 4; i++) {
        int m = m0 + 4*ty + i;
        float* orow = out + (size_t)m * EE + n0 + 4*tx;
        *(float4*)orow = make_float4(acc[i][0] + bvals[0], acc[i][1] + bvals[1],
                                     acc[i][2] + bvals[2], acc[i][3] + bvals[3]);
    }
}

// ---------------------------------------------------------------------------
extern "C" void kernel_launch(void* const* d_in, const int* in_sizes, int n_in,
                              void* d_out, int out_size)
{
    const float* x  = (const float*)d_in[0];
    const float* Wq = (const float*)d_in[1];
    const float* bq = (const float*)d_in[2];
    const float* Wk = (const float*)d_in[3];
    const float* bk = (const float*)d_in[4];
    const float* Wv = (const float*)d_in[5];
    const float* bv = (const float*)d_in[6];
    const float* Wo = (const float*)d_in[7];
    const float* bo = (const float*)d_in[8];
    float* out = (float*)d_out;

    qkv_kernel<<<dim3(MM/64, 3*HH), 256>>>(x, Wq, bq, Wk, bk, Wv, bv);

    const int smem = 3 * 64 * SMLD * (int)sizeof(float);
    cudaFuncSetAttribute(attn_kernel, cudaFuncAttributeMaxDynamicSharedMemorySize, smem);
    attn_kernel<<<dim3(SS/64, BB*HH), 256, smem>>>();

    oproj_kernel<<<dim3(MM/64, EE/64), 256>>>(Wo, bo, out);
}

// round 5
// speedup vs baseline: 3.1109x; 3.1109x over previous
#include <cuda_runtime.h>
#include <math.h>

#define BB 4
#define SS 2048
#define EE 1024
#define HH 16
#define DH 64
#define MM (BB*SS)        // 8192

// Scratch (allocation-free rule: __device__ globals). q/k/vt hold tf32-rounded floats.
__device__ float g_q [(size_t)BB*HH*SS*DH];  // [bh][s][d], pre-scaled by 0.125, tf32
__device__ float g_k [(size_t)BB*HH*SS*DH];  // [bh][s][d], tf32
__device__ float g_vt[(size_t)BB*HH*DH*SS];  // [bh][d][s], tf32 (transposed V)
__device__ float g_z [(size_t)BB*SS*HH*DH];  // [b][s][h*64+d], fp32

__device__ __forceinline__ unsigned tf32cvt(float x) {
    unsigned u; asm("cvt.rna.tf32.f32 %0, %1;" : "=r"(u) : "f"(x)); return u;
}
__device__ __forceinline__ unsigned fu(float x) { return __float_as_uint(x); }

__device__ __forceinline__ void mma8(float* c, const unsigned* a, const unsigned* b) {
    asm volatile(
        "mma.sync.aligned.m16n8k8.row.col.f32.tf32.tf32.f32 "
        "{%0,%1,%2,%3},{%4,%5,%6,%7},{%8,%9},{%0,%1,%2,%3};\n"
        : "+f"(c[0]), "+f"(c[1]), "+f"(c[2]), "+f"(c[3])
        : "r"(a[0]), "r"(a[1]), "r"(a[2]), "r"(a[3]), "r"(b[0]), "r"(b[1]));
}

// ---------------------------------------------------------------------------
// Kernel 1: QKV projections via tf32 mma. grid (MM/128, 3*H), block 256.
// Block tile 128x64, K-step 32. Warps: 4(M) x 2(N), warp tile 32x32.
// q,k -> natural [s][d]; v -> transposed [d][s]. All tf32-rounded.
// ---------------------------------------------------------------------------
#define PA 36
#define PB 72
__global__ __launch_bounds__(256) void qkv_mma(
    const float* __restrict__ x,
    const float* __restrict__ Wq, const float* __restrict__ bq,
    const float* __restrict__ Wk, const float* __restrict__ bk,
    const float* __restrict__ Wv, const float* __restrict__ bv)
{
    __shared__ float As[128*PA];   // [m][k] pitch 36
    __shared__ float Bs[32*PB];    // [k][n] pitch 72

    const int m0  = blockIdx.x * 128;
    const int h   = blockIdx.y & (HH - 1);
    const int mat = blockIdx.y >> 4;      // 0=q 1=k 2=v

    const float* W; const float* bias;
    if (mat == 0)      { W = Wq + (size_t)h*EE*DH; bias = bq + h*DH; }
    else if (mat == 1) { W = Wk + (size_t)h*EE*DH; bias = bk + h*DH; }
    else               { W = Wv + (size_t)h*EE*DH; bias = bv + h*DH; }

    const int tid = threadIdx.x;
    const int lane = tid & 31, wid = tid >> 5;
    const int qr = lane >> 2, lc = lane & 3;
    const int wm = (wid >> 1) * 32, wn = (wid & 1) * 32;

    float acc[2][4][4] = {};

    for (int k0 = 0; k0 < EE; k0 += 32) {
        #pragma unroll
        for (int r = 0; r < 4; r++) {
            int idx = tid + r*256, m = idx >> 3, q = idx & 7;
            float4 v = *(const float4*)(x + (size_t)(m0 + m)*EE + k0 + 4*q);
            float4 cv = make_float4(__uint_as_float(tf32cvt(v.x)), __uint_as_float(tf32cvt(v.y)),
                                    __uint_as_float(tf32cvt(v.z)), __uint_as_float(tf32cvt(v.w)));
            *(float4*)&As[m*PA + 4*q] = cv;
        }
        #pragma unroll
        for (int r = 0; r < 2; r++) {
            int idx = tid + r*256, kk = idx >> 4, q = idx & 15;
            float4 v = *(const float4*)(W + (size_t)(k0 + kk)*DH + 4*q);
            float4 cv = make_float4(__uint_as_float(tf32cvt(v.x)), __uint_as_float(tf32cvt(v.y)),
                                    __uint_as_float(tf32cvt(v.z)), __uint_as_float(tf32cvt(v.w)));
            *(float4*)&Bs[kk*PB + 4*q] = cv;
        }
        __syncthreads();

        #pragma unroll
        for (int ks = 0; ks < 4; ks++) {
            const int kc = 8*ks + lc;
            unsigned af[2][4];
            #pragma unroll
            for (int ma = 0; ma < 2; ma++) {
                const int rb = (wm + 16*ma + qr)*PA;
                af[ma][0] = fu(As[rb + kc]);
                af[ma][1] = fu(As[rb + 8*PA + kc]);
                af[ma][2] = fu(As[rb + kc + 4]);
                af[ma][3] = fu(As[rb + 8*PA + kc + 4]);
            }
            #pragma unroll
            for (int na = 0; na < 4; na++) {
                const int col = wn + 8*na + qr;
                unsigned bf[2];
                bf[0] = fu(Bs[(8*ks + lc)*PB + col]);
                bf[1] = fu(Bs[(8*ks + 4 + lc)*PB + col]);
                mma8(acc[0][na], af[0], bf);
                mma8(acc[1][na], af[1], bf);
            }
        }
        __syncthreads();
    }

    const int bb = m0 >> 11;
    const int bh = bb*HH + h;
    const float scale = (mat == 0) ? 0.125f : 1.0f;

    #pragma unroll
    for (int ma = 0; ma < 2; ma++) {
        const int r0 = m0 + wm + 16*ma + qr;       // global m
        const int s0l = r0 & (SS - 1);
        #pragma unroll
        for (int na = 0; na < 4; na++) {
            const int col = wn + 8*na + 2*lc;
            float b0 = bias[col], b1 = bias[col + 1];
            float v00 = (acc[ma][na][0] + b0) * scale;
            float v01 = (acc[ma][na][1] + b1) * scale;
            float v10 = (acc[ma][na][2] + b0) * scale;
            float v11 = (acc[ma][na][3] + b1) * scale;
            if (mat < 2) {
                float* g = (mat == 0) ? g_q : g_k;
                float* p0 = g + ((size_t)bh*SS + s0l) * DH + col;
                float* p1 = g + ((size_t)bh*SS + s0l + 8) * DH + col;
                *(float2*)p0 = make_float2(__uint_as_float(tf32cvt(v00)), __uint_as_float(tf32cvt(v01)));
                *(float2*)p1 = make_float2(__uint_as_float(tf32cvt(v10)), __uint_as_float(tf32cvt(v11)));
            } else {
                float* base = g_vt + (size_t)bh*DH*SS;
                base[(size_t)(col    )*SS + s0l    ] = __uint_as_float(tf32cvt(v00));
                base[(size_t)(col + 1)*SS + s0l    ] = __uint_as_float(tf32cvt(v01));
                base[(size_t)(col    )*SS + s0l + 8] = __uint_as_float(tf32cvt(v10));
                base[(size_t)(col + 1)*SS + s0l + 8] = __uint_as_float(tf32cvt(v11));
            }
        }
    }
}

// ---------------------------------------------------------------------------
// Kernel 2: flash attention via tf32 mma. grid (SS/128, B*H), block 256.
// Q tile 128, key tiles 64. 8 warps, warp w owns query rows [16w, 16w+16).
// ---------------------------------------------------------------------------
#define PQ 68
__global__ __launch_bounds__(256) void attn_mma()
{
    extern __shared__ float sm[];
    float* Qs  = sm;                    // [128][68]
    float* Ks  = sm + 128*PQ;           // [64][68]   K[t][d]
    float* Vts = sm + 128*PQ + 64*PQ;   // [64][68]   Vt[d][t]
    float* Ps  = sm + 128*PQ + 128*PQ;  // [128][68]  P[m][t]

    const int s0 = blockIdx.x * 128;
    const int bh = blockIdx.y;
    const int tid = threadIdx.x;
    const int lane = tid & 31, w = tid >> 5;
    const int qr = lane >> 2, lc = lane & 3;
    const int rowb = 16*w + qr;

    const float* qp  = g_q  + (size_t)bh*SS*DH;
    const float* kp  = g_k  + (size_t)bh*SS*DH;
    const float* vtp = g_vt + (size_t)bh*DH*SS;

    #pragma unroll
    for (int r = 0; r < 8; r++) {
        int idx = tid + r*256, m = idx >> 4, q = idx & 15;
        *(float4*)&Qs[m*PQ + 4*q] = *(const float4*)(qp + (size_t)(s0 + m)*DH + 4*q);
    }

    float mx0 = -1e30f, mx1 = -1e30f, l0 = 0.f, l1 = 0.f;
    float o[8][4] = {};

    for (int t0 = 0; t0 < SS; t0 += 64) {
        #pragma unroll
        for (int r = 0; r < 4; r++) {
            int idx = tid + r*256, a = idx >> 4, q = idx & 15;
            *(float4*)&Ks [a*PQ + 4*q] = *(const float4*)(kp  + (size_t)(t0 + a)*DH + 4*q);
            *(float4*)&Vts[a*PQ + 4*q] = *(const float4*)(vtp + (size_t)a*SS + t0 + 4*q);
        }
        __syncthreads();

        // S = Q K^T
        float s[8][4] = {};
        #pragma unroll
        for (int ks = 0; ks < 8; ks++) {
            const int kc = 8*ks + lc;
            unsigned a[4] = { fu(Qs[rowb*PQ + kc]),      fu(Qs[(rowb+8)*PQ + kc]),
                              fu(Qs[rowb*PQ + kc + 4]),  fu(Qs[(rowb+8)*PQ + kc + 4]) };
            #pragma unroll
            for (int na = 0; na < 8; na++) {
                unsigned b[2] = { fu(Ks[(8*na + qr)*PQ + kc]), fu(Ks[(8*na + qr)*PQ + kc + 4]) };
                mma8(s[na], a, b);
            }
        }

        // online softmax (rows rowb and rowb+8, fully warp-local)
        float rm0 = -1e30f, rm1 = -1e30f;
        #pragma unroll
        for (int na = 0; na < 8; na++) {
            rm0 = fmaxf(rm0, fmaxf(s[na][0], s[na][1]));
            rm1 = fmaxf(rm1, fmaxf(s[na][2], s[na][3]));
        }
        #pragma unroll
        for (int msk = 1; msk <= 2; msk <<= 1) {
            rm0 = fmaxf(rm0, __shfl_xor_sync(0xffffffffu, rm0, msk));
            rm1 = fmaxf(rm1, __shfl_xor_sync(0xffffffffu, rm1, msk));
        }
        float mn0 = fmaxf(mx0, rm0), mn1 = fmaxf(mx1, rm1);
        float a0 = __expf(mx0 - mn0), a1 = __expf(mx1 - mn1);
        mx0 = mn0; mx1 = mn1;
        float rs0 = 0.f, rs1 = 0.f;
        #pragma unroll
        for (int na = 0; na < 8; na++) {
            s[na][0] = __expf(s[na][0] - mn0); rs0 += s[na][0];
            s[na][1] = __expf(s[na][1] - mn0); rs0 += s[na][1];
            s[na][2] = __expf(s[na][2] - mn1); rs1 += s[na][2];
            s[na][3] = __expf(s[na][3] - mn1); rs1 += s[na][3];
        }
        #pragma unroll
        for (int msk = 1; msk <= 2; msk <<= 1) {
            rs0 += __shfl_xor_sync(0xffffffffu, rs0, msk);
            rs1 += __shfl_xor_sync(0xffffffffu, rs1, msk);
        }
        l0 = l0*a0 + rs0;  l1 = l1*a1 + rs1;
        #pragma unroll
        for (int na = 0; na < 8; na++) {
            o[na][0] *= a0; o[na][1] *= a0; o[na][2] *= a1; o[na][3] *= a1;
            *(float2*)&Ps[rowb*PQ + 8*na + 2*lc] =
                make_float2(__uint_as_float(tf32cvt(s[na][0])), __uint_as_float(tf32cvt(s[na][1])));
            *(float2*)&Ps[(rowb+8)*PQ + 8*na + 2*lc] =
                make_float2(__uint_as_float(tf32cvt(s[na][2])), __uint_as_float(tf32cvt(s[na][3])));
        }
        __syncwarp();

        // O += P V
        #pragma unroll
        for (int ks = 0; ks < 8; ks++) {
            const int kc = 8*ks + lc;
            unsigned a[4] = { fu(Ps[rowb*PQ + kc]),     fu(Ps[(rowb+8)*PQ + kc]),
                              fu(Ps[rowb*PQ + kc + 4]), fu(Ps[(rowb+8)*PQ + kc + 4]) };
            #pragma unroll
            for (int na = 0; na < 8; na++) {
                unsigned b[2] = { fu(Vts[(8*na + qr)*PQ + kc]), fu(Vts[(8*na + qr)*PQ + kc + 4]) };
                mma8(o[na], a, b);
            }
        }
        __syncthreads();
    }

    const float inv0 = 1.0f / l0, inv1 = 1.0f / l1;
    const int bb = bh >> 4, h = bh & 15;
    #pragma unroll
    for (int na = 0; na < 8; na++) {
        const int col = h*DH + 8*na + 2*lc;
        float* p0 = g_z + ((size_t)bb*SS + s0 + rowb) * (HH*DH) + col;
        float* p1 = g_z + ((size_t)bb*SS + s0 + rowb + 8) * (HH*DH) + col;
        *(float2*)p0 = make_float2(o[na][0]*inv0, o[na][1]*inv0);
        *(float2*)p1 = make_float2(o[na][2]*inv1, o[na][3]*inv1);
    }
}

// ---------------------------------------------------------------------------
// Kernel 3: output projection via tf32 mma. grid (MM/128, EE/64), block 256.
// out[8192,1024] = g_z @ Wo + bo  (fp32 out)
// ---------------------------------------------------------------------------
__global__ __launch_bounds__(256) void oproj_mma(
    const float* __restrict__ Wo, const float* __restrict__ bo,
    float* __restrict__ out)
{
    __shared__ float As[128*PA];
    __shared__ float Bs[32*PB];

    const int m0 = blockIdx.x * 128;
    const int n0 = blockIdx.y * 64;
    const int tid = threadIdx.x;
    const int lane = tid & 31, wid = tid >> 5;
    const int qr = lane >> 2, lc = lane & 3;
    const int wm = (wid >> 1) * 32, wn = (wid & 1) * 32;

    float acc[2][4][4] = {};

    for (int k0 = 0; k0 < HH*DH; k0 += 32) {
        #pragma unroll
        for (int r = 0; r < 4; r++) {
            int idx = tid + r*256, m = idx >> 3, q = idx & 7;
            float4 v = *(const float4*)(g_z + (size_t)(m0 + m)*(HH*DH) + k0 + 4*q);
            float4 cv = make_float4(__uint_as_float(tf32cvt(v.x)), __uint_as_float(tf32cvt(v.y)),
                                    __uint_as_float(tf32cvt(v.z)), __uint_as_float(tf32cvt(v.w)));
            *(float4*)&As[m*PA + 4*q] = cv;
        }
        #pragma unroll
        for (int r = 0; r < 2; r++) {
            int idx = tid + r*256, kk = idx >> 4, q = idx & 15;
            float4 v = *(const float4*)(Wo + (size_t)(k0 + kk)*EE + n0 + 4*q);
            float4 cv = make_float4(__uint_as_float(tf32cvt(v.x)), __uint_as_float(tf32cvt(v.y)),
                                    __uint_as_float(tf32cvt(v.z)), __uint_as_float(tf32cvt(v.w)));
            *(float4*)&Bs[kk*PB + 4*q] = cv;
        }
        __syncthreads();

        #pragma unroll
        for (int ks = 0; ks < 4; ks++) {
            const int kc = 8*ks + lc;
            unsigned af[2][4];
            #pragma unroll
            for (int ma = 0; ma < 2; ma++) {
                const int rb = (wm + 16*ma + qr)*PA;
                af[ma][0] = fu(As[rb + kc]);
                af[ma][1] = fu(As[rb + 8*PA + kc]);
                af[ma][2] = fu(As[rb + kc + 4]);
                af[ma][3] = fu(As[rb + 8*PA + kc + 4]);
            }
            #pragma unroll
            for (int na = 0; na < 4; na++) {
                const int col = wn + 8*na + qr;
                unsigned bf[2];
                bf[0] = fu(Bs[(8*ks + lc)*PB + col]);
                bf[1] = fu(Bs[(8*ks + 4 + lc)*PB + col]);
                mma8(acc[0][na], af[0], bf);
                mma8(acc[1][na], af[1], bf);
            }
        }
        __syncthreads();
    }

    #pragma unroll
    for (int ma = 0; ma < 2; ma++) {
        const int r0 = m0 + wm + 16*ma + qr;
        #pragma unroll
        for (int na = 0; na < 4; na++) {
            const int col = n0 + wn + 8*na + 2*lc;
            float b0 = bo[col], b1 = bo[col + 1];
            float* p0 = out + (size_t)r0*EE + col;
            float* p1 = out + (size_t)(r0 + 8)*EE + col;
            *(float2*)p0 = make_float2(acc[ma][na][0] + b0, acc[ma][na][1] + b1);
            *(float2*)p1 = make_float2(acc[ma][na][2] + b0, acc[ma][na][3] + b1);
        }
    }
}

// ---------------------------------------------------------------------------
extern "C" void kernel_launch(void* const* d_in, const int* in_sizes, int n_in,
                              void* d_out, int out_size)
{
    const float* x  = (const float*)d_in[0];
    const float* Wq = (const float*)d_in[1];
    const float* bq = (const float*)d_in[2];
    const float* Wk = (const float*)d_in[3];
    const float* bk = (const float*)d_in[4];
    const float* Wv = (const float*)d_in[5];
    const float* bv = (const float*)d_in[6];
    const float* Wo = (const float*)d_in[7];
    const float* bo = (const float*)d_in[8];
    float* out = (float*)d_out;

    qkv_mma<<<dim3(MM/128, 3*HH), 256>>>(x, Wq, bq, Wk, bk, Wv, bv);

    const int smem = (128*PQ + 64*PQ + 64*PQ + 128*PQ) * (int)sizeof(float);  // 104448 B
    cudaFuncSetAttribute(attn_mma, cudaFuncAttributeMaxDynamicSharedMemorySize, smem);
    attn_mma<<<dim3(SS/128, BB*HH), 256, smem>>>();

    oproj_mma<<<dim3(MM/128, EE/64), 256>>>(Wo, bo, out);
}

// round 6
// speedup vs baseline: 3.3225x; 1.0680x over previous
#include <cuda_runtime.h>
#include <math.h>

#define BB 4
#define SS 2048
#define EE 1024
#define HH 16
#define DH 64
#define MM (BB*SS)        // 8192

// Scratch (allocation-free rule: __device__ globals)
__device__ __align__(256) float g_xr[(size_t)MM*EE];          // tf32-rounded x
__device__ __align__(256) float g_wr[(size_t)3*HH*EE*DH];     // rounded 0.125*Wq | Wk | Wv
__device__ __align__(256) float g_wor[(size_t)EE*EE];         // rounded Wo
__device__ __align__(256) float g_q [(size_t)BB*HH*SS*DH];    // [bh][s][d], tf32, q pre-scaled
__device__ __align__(256) float g_k [(size_t)BB*HH*SS*DH];    // [bh][s][d], tf32
__device__ __align__(256) float g_vt[(size_t)BB*HH*DH*SS];    // [bh][d][s], tf32
__device__ __align__(256) float g_z [(size_t)BB*SS*HH*DH];    // [b][s][h*64+d], tf32

__device__ __forceinline__ unsigned tf32cvt(float x) {
    unsigned u; asm("cvt.rna.tf32.f32 %0, %1;" : "=r"(u) : "f"(x)); return u;
}
__device__ __forceinline__ float tf32r(float x) { return __uint_as_float(tf32cvt(x)); }
__device__ __forceinline__ unsigned fu(float x) { return __float_as_uint(x); }

__device__ __forceinline__ void mma8(float* c, const unsigned* a, const unsigned* b) {
    asm volatile(
        "mma.sync.aligned.m16n8k8.row.col.f32.tf32.tf32.f32 "
        "{%0,%1,%2,%3},{%4,%5,%6,%7},{%8,%9},{%0,%1,%2,%3};\n"
        : "+f"(c[0]), "+f"(c[1]), "+f"(c[2]), "+f"(c[3])
        : "r"(a[0]), "r"(a[1]), "r"(a[2]), "r"(a[3]), "r"(b[0]), "r"(b[1]));
}

__device__ __forceinline__ void cpa16(unsigned dst, const float* src) {
    asm volatile("cp.async.cg.shared.global [%0], [%1], 16;\n" :: "r"(dst), "l"(src));
}
__device__ __forceinline__ void cpa_commit() { asm volatile("cp.async.commit_group;\n"); }

// ---------------------------------------------------------------------------
// Kernel 0: pre-round inputs to tf32 (rna). Segments: x | 0.125*Wq | Wk | Wv | Wo
// grid 12288 x 256, 4 floats/thread.
// ---------------------------------------------------------------------------
__global__ __launch_bounds__(256) void prep_kernel(
    const float* __restrict__ x,  const float* __restrict__ Wq,
    const float* __restrict__ Wk, const float* __restrict__ Wv,
    const float* __restrict__ Wo)
{
    const size_t W1 = (size_t)HH*EE*DH;      // 1048576
    size_t i = ((size_t)blockIdx.x * 256 + threadIdx.x) * 4;
    const float* src; float* dst; float sc = 1.0f; size_t j;
    if (i < (size_t)MM*EE)            { src = x;  dst = g_xr;        j = i; }
    else if (i < (size_t)MM*EE + W1)  { src = Wq; dst = g_wr;        j = i - (size_t)MM*EE; sc = 0.125f; }
    else if (i < (size_t)MM*EE + 2*W1){ src = Wk; dst = g_wr + W1;   j = i - (size_t)MM*EE - W1; }
    else if (i < (size_t)MM*EE + 3*W1){ src = Wv; dst = g_wr + 2*W1; j = i - (size_t)MM*EE - 2*W1; }
    else                              { src = Wo; dst = g_wor;       j = i - (size_t)MM*EE - 3*W1; }
    float4 v = *(const float4*)(src + j);
    *(float4*)(dst + j) = make_float4(tf32r(v.x * sc), tf32r(v.y * sc),
                                      tf32r(v.z * sc), tf32r(v.w * sc));
}

// ---------------------------------------------------------------------------
// GEMM tile constants: block 128x128, 8 warps (2M x 4N), warp 64x32, K-step 16,
// 2-stage cp.async double buffer. PA/PB chosen bank-conflict-free.
// ---------------------------------------------------------------------------
#define PA 20
#define PB 136
#define ASZ (128*PA)    // floats per A stage
#define BSZ (16*PB)     // floats per B stage

#define GEMM_COMPUTE(as, bs)                                                   \
    _Pragma("unroll")                                                          \
    for (int ks = 0; ks < 2; ks++) {                                           \
        const int kc = 8*ks + lc;                                              \
        unsigned af[4][4];                                                     \
        _Pragma("unroll")                                                      \
        for (int ma = 0; ma < 4; ma++) {                                       \
            const float* ap = (as) + (wm + 16*ma + qr)*PA;                     \
            af[ma][0] = fu(ap[kc]);       af[ma][1] = fu(ap[8*PA + kc]);       \
            af[ma][2] = fu(ap[kc + 4]);   af[ma][3] = fu(ap[8*PA + kc + 4]);   \
        }                                                                      \
        _Pragma("unroll")                                                      \
        for (int na = 0; na < 4; na++) {                                       \
            const int col = wn + 8*na + qr;                                    \
            unsigned bf[2] = { fu((bs)[(8*ks + lc)*PB + col]),                 \
                               fu((bs)[(8*ks + 4 + lc)*PB + col]) };           \
            _Pragma("unroll")                                                  \
            for (int ma = 0; ma < 4; ma++) mma8(acc[ma][na], af[ma], bf);      \
        }                                                                      \
    }

// ---------------------------------------------------------------------------
// Kernel 1: QKV projections. grid (64, 24): y -> (mat = y>>3, head-pair = y&7).
// C[128 rows x 128 cols(=2 heads)] = xr @ Wr. Epilogue: +bias, round, write
// q/k natural [s][d], v transposed [d][s].
// ---------------------------------------------------------------------------
__global__ __launch_bounds__(256) void qkv_mma2(
    const float* __restrict__ bq, const float* __restrict__ bk,
    const float* __restrict__ bv)
{
    __shared__ float As[2*ASZ];
    __shared__ float Bs[2*BSZ];

    const int m0  = blockIdx.x * 128;
    const int mat = blockIdx.y >> 3;
    const int hp  = blockIdx.y & 7;

    const int tid = threadIdx.x;
    const int lane = tid & 31, wid = tid >> 5;
    const int qr = lane >> 2, lc = lane & 3;
    const int wm = (wid >> 2) * 64, wn = (wid & 3) * 32;

    // per-thread loader coords
    const int a_m0 = tid >> 2,           a_k  = (tid & 3) * 4;       // +64 rows for 2nd
    const int b_k0 = tid >> 5,           b_n  = (tid & 31) * 4;      // +8 k-rows for 2nd
    const float* asrc0 = g_xr + (size_t)(m0 + a_m0)      * EE + a_k;
    const float* asrc1 = g_xr + (size_t)(m0 + a_m0 + 64) * EE + a_k;
    const float* wmat  = g_wr + (size_t)mat * (HH*EE*DH);
    const int head = 2*hp + (b_n >> 6), bnl = b_n & 63;
    const float* bsrc0 = wmat + (size_t)head*(EE*DH) + (size_t)(b_k0    )*DH + bnl;
    const float* bsrc1 = wmat + (size_t)head*(EE*DH) + (size_t)(b_k0 + 8)*DH + bnl;

    const unsigned sA = (unsigned)__cvta_generic_to_shared(As);
    const unsigned sB = (unsigned)__cvta_generic_to_shared(Bs);
    const unsigned dA0 = sA + ((a_m0     )*PA + a_k)*4;
    const unsigned dA1 = sA + ((a_m0 + 64)*PA + a_k)*4;
    const unsigned dB0 = sB + ((b_k0     )*PB + b_n)*4;
    const unsigned dB1 = sB + ((b_k0 + 8 )*PB + b_n)*4;

    float acc[4][4][4] = {};

    // prologue: stage 0, k=0
    cpa16(dA0, asrc0); cpa16(dA1, asrc1);
    cpa16(dB0, bsrc0); cpa16(dB1, bsrc1);
    cpa_commit();

    for (int kt = 0; kt < EE/16; kt++) {
        const int st = kt & 1;
        if (kt + 1 < EE/16) {
            const int sn = (kt + 1) & 1;
            const float* ao = (size_t)(kt+1)*16 + (const float*)0;  (void)ao;
            cpa16(dA0 + sn*ASZ*4, asrc0 + (kt+1)*16);
            cpa16(dA1 + sn*ASZ*4, asrc1 + (kt+1)*16);
            cpa16(dB0 + sn*BSZ*4, bsrc0 + (size_t)(kt+1)*16*DH);
            cpa16(dB1 + sn*BSZ*4, bsrc1 + (size_t)(kt+1)*16*DH);
            cpa_commit();
            asm volatile("cp.async.wait_group 1;\n");
        } else {
            asm volatile("cp.async.wait_group 0;\n");
        }
        __syncthreads();
        GEMM_COMPUTE(As + st*ASZ, Bs + st*BSZ)
        __syncthreads();
    }

    // epilogue
    const int bb = m0 >> 11;
    const float* biasm = (mat == 0) ? bq : (mat == 1) ? bk : bv;
    const float bsc = (mat == 0) ? 0.125f : 1.0f;

    #pragma unroll
    for (int ma = 0; ma < 4; ma++) {
        const int r0 = m0 + wm + 16*ma + qr;
        const int s  = r0 & (SS - 1);
        #pragma unroll
        for (int na = 0; na < 4; na++) {
            const int col = wn + 8*na + 2*lc;      // 0..126, even
            const int hs = col >> 6, d = col & 63;
            const int bh = bb*HH + 2*hp + hs;
            const float* bp = biasm + (2*hp + hs)*DH;
            const float b0 = bsc * bp[d], b1 = bsc * bp[d+1];
            const float v00 = tf32r(acc[ma][na][0] + b0);
            const float v01 = tf32r(acc[ma][na][1] + b1);
            const float v10 = tf32r(acc[ma][na][2] + b0);
            const float v11 = tf32r(acc[ma][na][3] + b1);
            if (mat < 2) {
                float* g = (mat == 0) ? g_q : g_k;
                *(float2*)(g + ((size_t)bh*SS + s    )*DH + d) = make_float2(v00, v01);
                *(float2*)(g + ((size_t)bh*SS + s + 8)*DH + d) = make_float2(v10, v11);
            } else {
                float* base = g_vt + (size_t)bh*DH*SS;
                base[(size_t)(d    )*SS + s    ] = v00;
                base[(size_t)(d + 1)*SS + s    ] = v01;
                base[(size_t)(d    )*SS + s + 8] = v10;
                base[(size_t)(d + 1)*SS + s + 8] = v11;
            }
        }
    }
}

// ---------------------------------------------------------------------------
// Kernel 2: flash attention via tf32 mma. grid (SS/128, B*H), block 256.
// Inputs are tf32-clean; P rounded before smem; z rounded at store.
// ---------------------------------------------------------------------------
#define PQ 68
__global__ __launch_bounds__(256) void attn_mma()
{
    extern __shared__ float sm[];
    float* Qs  = sm;                    // [128][68]
    float* Ks  = sm + 128*PQ;           // [64][68]   K[t][d]
    float* Vts = sm + 128*PQ + 64*PQ;   // [64][68]   Vt[d][t]
    float* Ps  = sm + 128*PQ + 128*PQ;  // [128][68]  P[m][t]

    const int s0 = blockIdx.x * 128;
    const int bh = blockIdx.y;
    const int tid = threadIdx.x;
    const int lane = tid & 31, w = tid >> 5;
    const int qr = lane >> 2, lc = lane & 3;
    const int rowb = 16*w + qr;

    const float* qp  = g_q  + (size_t)bh*SS*DH;
    const float* kp  = g_k  + (size_t)bh*SS*DH;
    const float* vtp = g_vt + (size_t)bh*DH*SS;

    #pragma unroll
    for (int r = 0; r < 8; r++) {
        int idx = tid + r*256, m = idx >> 4, q = idx & 15;
        *(float4*)&Qs[m*PQ + 4*q] = *(const float4*)(qp + (size_t)(s0 + m)*DH + 4*q);
    }

    float mx0 = -1e30f, mx1 = -1e30f, l0 = 0.f, l1 = 0.f;
    float o[8][4] = {};

    for (int t0 = 0; t0 < SS; t0 += 64) {
        #pragma unroll
        for (int r = 0; r < 4; r++) {
            int idx = tid + r*256, a = idx >> 4, q = idx & 15;
            *(float4*)&Ks [a*PQ + 4*q] = *(const float4*)(kp  + (size_t)(t0 + a)*DH + 4*q);
            *(float4*)&Vts[a*PQ + 4*q] = *(const float4*)(vtp + (size_t)a*SS + t0 + 4*q);
        }
        __syncthreads();

        // S = Q K^T
        float s[8][4] = {};
        #pragma unroll
        for (int ks = 0; ks < 8; ks++) {
            const int kc = 8*ks + lc;
            unsigned a[4] = { fu(Qs[rowb*PQ + kc]),      fu(Qs[(rowb+8)*PQ + kc]),
                              fu(Qs[rowb*PQ + kc + 4]),  fu(Qs[(rowb+8)*PQ + kc + 4]) };
            #pragma unroll
            for (int na = 0; na < 8; na++) {
                unsigned b[2] = { fu(Ks[(8*na + qr)*PQ + kc]), fu(Ks[(8*na + qr)*PQ + kc + 4]) };
                mma8(s[na], a, b);
            }
        }

        // online softmax (rows rowb, rowb+8 — warp-local, lanes lc 0..3 share row)
        float rm0 = -1e30f, rm1 = -1e30f;
        #pragma unroll
        for (int na = 0; na < 8; na++) {
            rm0 = fmaxf(rm0, fmaxf(s[na][0], s[na][1]));
            rm1 = fmaxf(rm1, fmaxf(s[na][2], s[na][3]));
        }
        #pragma unroll
        for (int msk = 1; msk <= 2; msk <<= 1) {
            rm0 = fmaxf(rm0, __shfl_xor_sync(0xffffffffu, rm0, msk));
            rm1 = fmaxf(rm1, __shfl_xor_sync(0xffffffffu, rm1, msk));
        }
        float mn0 = fmaxf(mx0, rm0), mn1 = fmaxf(mx1, rm1);
        float a0 = __expf(mx0 - mn0), a1 = __expf(mx1 - mn1);
        mx0 = mn0; mx1 = mn1;
        float rs0 = 0.f, rs1 = 0.f;
        #pragma unroll
        for (int na = 0; na < 8; na++) {
            s[na][0] = __expf(s[na][0] - mn0); rs0 += s[na][0];
            s[na][1] = __expf(s[na][1] - mn0); rs0 += s[na][1];
            s[na][2] = __expf(s[na][2] - mn1); rs1 += s[na][2];
            s[na][3] = __expf(s[na][3] - mn1); rs1 += s[na][3];
        }
        #pragma unroll
        for (int msk = 1; msk <= 2; msk <<= 1) {
            rs0 += __shfl_xor_sync(0xffffffffu, rs0, msk);
            rs1 += __shfl_xor_sync(0xffffffffu, rs1, msk);
        }
        l0 = l0*a0 + rs0;  l1 = l1*a1 + rs1;
        #pragma unroll
        for (int na = 0; na < 8; na++) {
            o[na][0] *= a0; o[na][1] *= a0; o[na][2] *= a1; o[na][3] *= a1;
            *(float2*)&Ps[rowb*PQ + 8*na + 2*lc] =
                make_float2(tf32r(s[na][0]), tf32r(s[na][1]));
            *(float2*)&Ps[(rowb+8)*PQ + 8*na + 2*lc] =
                make_float2(tf32r(s[na][2]), tf32r(s[na][3]));
        }
        __syncwarp();

        // O += P V
        #pragma unroll
        for (int ks = 0; ks < 8; ks++) {
            const int kc = 8*ks + lc;
            unsigned a[4] = { fu(Ps[rowb*PQ + kc]),     fu(Ps[(rowb+8)*PQ + kc]),
                              fu(Ps[rowb*PQ + kc + 4]), fu(Ps[(rowb+8)*PQ + kc + 4]) };
            #pragma unroll
            for (int na = 0; na < 8; na++) {
                unsigned b[2] = { fu(Vts[(8*na + qr)*PQ + kc]), fu(Vts[(8*na + qr)*PQ + kc + 4]) };
                mma8(o[na], a, b);
            }
        }
        __syncthreads();
    }

    const float inv0 = 1.0f / l0, inv1 = 1.0f / l1;
    const int bb = bh >> 4, h = bh & 15;
    #pragma unroll
    for (int na = 0; na < 8; na++) {
        const int col = h*DH + 8*na + 2*lc;
        float* p0 = g_z + ((size_t)bb*SS + s0 + rowb) * (HH*DH) + col;
        float* p1 = g_z + ((size_t)bb*SS + s0 + rowb + 8) * (HH*DH) + col;
        *(float2*)p0 = make_float2(tf32r(o[na][0]*inv0), tf32r(o[na][1]*inv0));
        *(float2*)p1 = make_float2(tf32r(o[na][2]*inv1), tf32r(o[na][3]*inv1));
    }
}

// ---------------------------------------------------------------------------
// Kernel 3: output projection. grid (64, 8). out = g_z @ Wo + bo (fp32 out).
// Same pipelined GEMM as qkv.
// ---------------------------------------------------------------------------
__global__ __launch_bounds__(256) void oproj_mma2(
    const float* __restrict__ bo, float* __restrict__ out)
{
    __shared__ float As[2*ASZ];
    __shared__ float Bs[2*BSZ];

    const int m0 = blockIdx.x * 128;
    const int n0 = blockIdx.y * 128;

    const int tid = threadIdx.x;
    const int lane = tid & 31, wid = tid >> 5;
    const int qr = lane >> 2, lc = lane & 3;
    const int wm = (wid >> 2) * 64, wn = (wid & 3) * 32;

    const int a_m0 = tid >> 2,  a_k = (tid & 3) * 4;
    const int b_k0 = tid >> 5,  b_n = (tid & 31) * 4;
    const float* asrc0 = g_z + (size_t)(m0 + a_m0)      * EE + a_k;
    const float* asrc1 = g_z + (size_t)(m0 + a_m0 + 64) * EE + a_k;
    const float* bsrc0 = g_wor + (size_t)(b_k0    )*EE + n0 + b_n;
    const float* bsrc1 = g_wor + (size_t)(b_k0 + 8)*EE + n0 + b_n;

    const unsigned sA = (unsigned)__cvta_generic_to_shared(As);
    const unsigned sB = (unsigned)__cvta_generic_to_shared(Bs);
    const unsigned dA0 = sA + ((a_m0     )*PA + a_k)*4;
    const unsigned dA1 = sA + ((a_m0 + 64)*PA + a_k)*4;
    const unsigned dB0 = sB + ((b_k0     )*PB + b_n)*4;
    const unsigned dB1 = sB + ((b_k0 + 8 )*PB + b_n)*4;

    float acc[4][4][4] = {};

    cpa16(dA0, asrc0); cpa16(dA1, asrc1);
    cpa16(dB0, bsrc0); cpa16(dB1, bsrc1);
    cpa_commit();

    for (int kt = 0; kt < EE/16; kt++) {
        const int st = kt & 1;
        if (kt + 1 < EE/16) {
            const int sn = (kt + 1) & 1;
            cpa16(dA0 + sn*ASZ*4, asrc0 + (kt+1)*16);
            cpa16(dA1 + sn*ASZ*4, asrc1 + (kt+1)*16);
            cpa16(dB0 + sn*BSZ*4, bsrc0 + (size_t)(kt+1)*16*EE);
            cpa16(dB1 + sn*BSZ*4, bsrc1 + (size_t)(kt+1)*16*EE);
            cpa_commit();
            asm volatile("cp.async.wait_group 1;\n");
        } else {
            asm volatile("cp.async.wait_group 0;\n");
        }
        __syncthreads();
        GEMM_COMPUTE(As + st*ASZ, Bs + st*BSZ)
        __syncthreads();
    }

    #pragma unroll
    for (int ma = 0; ma < 4; ma++) {
        const int r0 = m0 + wm + 16*ma + qr;
        #pragma unroll
        for (int na = 0; na < 4; na++) {
            const int col = n0 + wn + 8*na + 2*lc;
            const float b0 = bo[col], b1 = bo[col + 1];
            *(float2*)(out + (size_t)r0*EE + col) =
                make_float2(acc[ma][na][0] + b0, acc[ma][na][1] + b1);
            *(float2*)(out + (size_t)(r0 + 8)*EE + col) =
                make_float2(acc[ma][na][2] + b0, acc[ma][na][3] + b1);
        }
    }
}

// ---------------------------------------------------------------------------
extern "C" void kernel_launch(void* const* d_in, const int* in_sizes, int n_in,
                              void* d_out, int out_size)
{
    const float* x  = (const float*)d_in[0];
    const float* Wq = (const float*)d_in[1];
    const float* bq = (const float*)d_in[2];
    const float* Wk = (const float*)d_in[3];
    const float* bk = (const float*)d_in[4];
    const float* Wv = (const float*)d_in[5];
    const float* bv = (const float*)d_in[6];
    const float* Wo = (const float*)d_in[7];
    const float* bo = (const float*)d_in[8];
    float* out = (float*)d_out;

    // total prep elements: 8M (x) + 4*1M (W) = 12582912 -> 12288 blocks * 1024 elems
    prep_kernel<<<12288, 256>>>(x, Wq, Wk, Wv, Wo);

    qkv_mma2<<<dim3(MM/128, 24), 256>>>(bq, bk, bv);

    const int smem = (128*PQ + 64*PQ + 64*PQ + 128*PQ) * (int)sizeof(float);  // 104448 B
    cudaFuncSetAttribute(attn_mma, cudaFuncAttributeMaxDynamicSharedMemorySize, smem);
    attn_mma<<<dim3(SS/128, BB*HH), 256, smem>>>();

    oproj_mma2<<<dim3(MM/128, EE/128), 256>>>(bo, out);
}

// round 8
// speedup vs baseline: 6.0584x; 1.8235x over previous
#include <cuda_runtime.h>
#include <cuda_fp16.h>
#include <math.h>

#define BB 4
#define SS 2048
#define EE 1024
#define HH 16
#define DH 64
#define MM (BB*SS)        // 8192

// ---------------------------------------------------------------------------
// Scratch (allocation-free rule: __device__ globals), all fp16
// ---------------------------------------------------------------------------
__device__ __align__(256) __half g_xh [(size_t)MM*EE];        // x, natural [m][e]
__device__ __align__(256) __half g_wh [(size_t)3*HH*EE*DH];   // 0.125Wq|Wk|Wv, kp2 per head
__device__ __align__(256) __half g_woh[(size_t)EE*EE];        // Wo, kp2
__device__ __align__(256) __half g_qh [(size_t)BB*HH*SS*DH];  // [bh][s][d], pre-scaled
__device__ __align__(256) __half g_kh [(size_t)BB*HH*SS*DH];  // [bh][s][d]
__device__ __align__(256) __half g_vth[(size_t)BB*HH*DH*SS];  // [bh][d][s]
__device__ __align__(256) __half g_zh [(size_t)BB*SS*HH*DH];  // [b][s][h*64+d]

__device__ __forceinline__ unsigned fuh(const __half* p) { return *(const unsigned*)p; }

__device__ __forceinline__ void mma16(float* c, const unsigned* a, const unsigned* b) {
    asm volatile(
        "mma.sync.aligned.m16n8k16.row.col.f32.f16.f16.f32 "
        "{%0,%1,%2,%3},{%4,%5,%6,%7},{%8,%9},{%0,%1,%2,%3};\n"
        : "+f"(c[0]), "+f"(c[1]), "+f"(c[2]), "+f"(c[3])
        : "r"(a[0]), "r"(a[1]), "r"(a[2]), "r"(a[3]), "r"(b[0]), "r"(b[1]));
}

__device__ __forceinline__ void cpa16(unsigned dst, const void* src) {
    asm volatile("cp.async.cg.shared.global [%0], [%1], 16;\n" :: "r"(dst), "l"(src));
}
__device__ __forceinline__ void cpa_commit() { asm volatile("cp.async.commit_group;\n"); }

// ---------------------------------------------------------------------------
// Kernel 0: convert inputs to fp16. x natural; weights to kp2 layout
// (addr = (k>>1)*(2N) + n*2 + (k&1)), Wq scaled by 0.125.
// grid 12288 x 256, 4 elements/thread.
// ---------------------------------------------------------------------------
__global__ __launch_bounds__(256) void prep_kernel(
    const float* __restrict__ x,  const float* __restrict__ Wq,
    const float* __restrict__ Wk, const float* __restrict__ Wv,
    const float* __restrict__ Wo)
{
    const size_t XN = (size_t)MM*EE;          // 8388608
    const size_t W1 = (size_t)HH*EE*DH;       // 1048576
    size_t i = ((size_t)blockIdx.x * 256 + threadIdx.x) * 4;

    if (i < XN) {
        float4 v = *(const float4*)(x + i);
        *(__half2*)(g_xh + i)     = __floats2half2_rn(v.x, v.y);
        *(__half2*)(g_xh + i + 2) = __floats2half2_rn(v.z, v.w);
    } else if (i < XN + 3*W1) {
        size_t j = i - XN;
        int mat = (int)(j / W1);
        size_t r = j - (size_t)mat * W1;
        int h  = (int)(r >> 16);             // /65536
        int rr = (int)(r & 65535);
        int k  = rr >> 6, n0 = rr & 63;
        const float* src = ((mat == 0) ? Wq : (mat == 1) ? Wk : Wv) + (size_t)h*(EE*DH) + (size_t)k*DH + n0;
        float sc = (mat == 0) ? 0.125f : 1.0f;
        __half* dst = g_wh + (size_t)mat*W1 + (size_t)h*(EE*DH) + (size_t)(k >> 1)*(2*DH) + (k & 1);
        float4 v = *(const float4*)src;
        dst[(n0    )*2] = __float2half_rn(v.x * sc);
        dst[(n0 + 1)*2] = __float2half_rn(v.y * sc);
        dst[(n0 + 2)*2] = __float2half_rn(v.z * sc);
        dst[(n0 + 3)*2] = __float2half_rn(v.w * sc);
    } else {
        size_t j = i - XN - 3*W1;
        int k = (int)(j >> 10), n0 = (int)(j & 1023);
        const float* src = Wo + (size_t)k*EE + n0;
        __half* dst = g_woh + (size_t)(k >> 1)*(2*EE) + (k & 1);
        float4 v = *(const float4*)src;
        dst[(n0    )*2] = __float2half_rn(v.x);
        dst[(n0 + 1)*2] = __float2half_rn(v.y);
        dst[(n0 + 2)*2] = __float2half_rn(v.z);
        dst[(n0 + 3)*2] = __float2half_rn(v.w);
    }
}

// ---------------------------------------------------------------------------
// GEMM: block 128x128, 8 warps (2M x 4N), warp 64x32, K-step 32 halves
// (2 mma-k of 16), 2-stage cp.async. A smem [m][k] pitch 40 halves;
// B smem kp2 [k2][2n] pitch 272 halves. Both verified conflict-free.
// ---------------------------------------------------------------------------
#define PAH 40
#define PBH 272
#define ASZH (128*PAH)   // 5120 halves / stage
#define BSZH (16*PBH)    // 4352 halves / stage

#define GEMM_COMPUTE16(as, bs)                                                 \
    _Pragma("unroll")                                                          \
    for (int ks = 0; ks < 2; ks++) {                                           \
        const int kk = 16*ks;                                                  \
        unsigned af[4][4];                                                     \
        _Pragma("unroll")                                                      \
        for (int ma = 0; ma < 4; ma++) {                                       \
            const __half* ap = (as) + (wm + 16*ma + qr)*PAH + kk + 2*lc;       \
            af[ma][0] = fuh(ap);                                               \
            af[ma][1] = fuh(ap + 8*PAH);                                       \
            af[ma][2] = fuh(ap + 8);                                           \
            af[ma][3] = fuh(ap + 8*PAH + 8);                                   \
        }                                                                      \
        _Pragma("unroll")                                                      \
        for (int na = 0; na < 4; na++) {                                       \
            const int col2 = (wn + 8*na + qr)*2;                               \
            const __half* bp = (bs) + (8*ks + lc)*PBH + col2;                  \
            unsigned bf[2] = { fuh(bp), fuh(bp + 4*PBH) };                     \
            _Pragma("unroll")                                                  \
            for (int ma = 0; ma < 4; ma++) mma16(acc[ma][na], af[ma], bf);     \
        }                                                                      \
    }

// ---------------------------------------------------------------------------
// Kernel 1: QKV projections. grid (64, 24): y -> (mat=y>>3, head-pair=y&7).
// ---------------------------------------------------------------------------
__global__ __launch_bounds__(256) void qkv_mma3(
    const float* __restrict__ bq, const float* __restrict__ bk,
    const float* __restrict__ bv)
{
    __shared__ __half As[2*ASZH];
    __shared__ __half Bs[2*BSZH];

    const int m0  = blockIdx.x * 128;
    const int mat = blockIdx.y >> 3;
    const int hp  = blockIdx.y & 7;

    const int tid = threadIdx.x;
    const int lane = tid & 31, wid = tid >> 5;
    const int qr = lane >> 2, lc = lane & 3;
    const int wm = (wid >> 2) * 64, wn = (wid & 3) * 32;

    // loaders: A 2 issues (idx>>2=row, idx&3=8-half chunk), B 2 issues
    const int a_row = tid >> 2,  a_q = (tid & 3) * 8;
    const int a_row2 = (tid + 256) >> 2, a_q2 = ((tid + 256) & 3) * 8;
    const int b_k2a = tid >> 5,  b_pa = tid & 31;
    const int b_k2b = (tid + 256) >> 5, b_pb = (tid + 256) & 31;

    const __half* wbase = g_wh + (size_t)mat*(HH*EE*DH);
    const __half* asrc0 = g_xh + (size_t)(m0 + a_row )*EE + a_q;
    const __half* asrc1 = g_xh + (size_t)(m0 + a_row2)*EE + a_q2;
    const __half* bsrc0 = wbase + (size_t)(2*hp + (b_pa >> 4))*(EE*DH) + (size_t)b_k2a*(2*DH) + (b_pa & 15)*8;
    const __half* bsrc1 = wbase + (size_t)(2*hp + (b_pb >> 4))*(EE*DH) + (size_t)b_k2b*(2*DH) + (b_pb & 15)*8;

    const unsigned sA = (unsigned)__cvta_generic_to_shared(As);
    const unsigned sB = (unsigned)__cvta_generic_to_shared(Bs);
    const unsigned dA0 = sA + (a_row *PAH + a_q )*2;
    const unsigned dA1 = sA + (a_row2*PAH + a_q2)*2;
    const unsigned dB0 = sB + (b_k2a*PBH + b_pa*8)*2;
    const unsigned dB1 = sB + (b_k2b*PBH + b_pb*8)*2;

    float acc[4][4][4] = {};

    cpa16(dA0, asrc0); cpa16(dA1, asrc1);
    cpa16(dB0, bsrc0); cpa16(dB1, bsrc1);
    cpa_commit();

    for (int kt = 0; kt < EE/32; kt++) {
        const int st = kt & 1;
        if (kt + 1 < EE/32) {
            const int sn = (kt + 1) & 1;
            cpa16(dA0 + sn*ASZH*2, asrc0 + (kt+1)*32);
            cpa16(dA1 + sn*ASZH*2, asrc1 + (kt+1)*32);
            cpa16(dB0 + sn*BSZH*2, bsrc0 + (size_t)(kt+1)*16*(2*DH));
            cpa16(dB1 + sn*BSZH*2, bsrc1 + (size_t)(kt+1)*16*(2*DH));
            cpa_commit();
            asm volatile("cp.async.wait_group 1;\n");
        } else {
            asm volatile("cp.async.wait_group 0;\n");
        }
        __syncthreads();
        GEMM_COMPUTE16(As + st*ASZH, Bs + st*BSZH)
        __syncthreads();
    }

    const int bb = m0 >> 11;
    const float* biasm = (mat == 0) ? bq : (mat == 1) ? bk : bv;
    const float bsc = (mat == 0) ? 0.125f : 1.0f;

    #pragma unroll
    for (int ma = 0; ma < 4; ma++) {
        const int r0 = m0 + wm + 16*ma + qr;
        const int s  = r0 & (SS - 1);
        #pragma unroll
        for (int na = 0; na < 4; na++) {
            const int col = wn + 8*na + 2*lc;          // 0..126 even
            const int hs = col >> 6, d = col & 63;
            const int bh = bb*HH + 2*hp + hs;
            const float* bp = biasm + (2*hp + hs)*DH;
            const float b0 = bsc * bp[d], b1 = bsc * bp[d+1];
            if (mat < 2) {
                __half* g = (mat == 0) ? g_qh : g_kh;
                *(__half2*)(g + ((size_t)bh*SS + s    )*DH + d) =
                    __floats2half2_rn(acc[ma][na][0] + b0, acc[ma][na][1] + b1);
                *(__half2*)(g + ((size_t)bh*SS + s + 8)*DH + d) =
                    __floats2half2_rn(acc[ma][na][2] + b0, acc[ma][na][3] + b1);
            } else {
                __half* base = g_vth + (size_t)bh*DH*SS;
                base[(size_t)(d    )*SS + s    ] = __float2half_rn(acc[ma][na][0] + b0);
                base[(size_t)(d + 1)*SS + s    ] = __float2half_rn(acc[ma][na][1] + b1);
                base[(size_t)(d    )*SS + s + 8] = __float2half_rn(acc[ma][na][2] + b0);
                base[(size_t)(d + 1)*SS + s + 8] = __float2half_rn(acc[ma][na][3] + b1);
            }
        }
    }
}

// ---------------------------------------------------------------------------
// Kernel 2: flash attention, fp16 m16n8k16. grid (SS/128, B*H), block 256.
// ---------------------------------------------------------------------------
#define PQH 72
__global__ __launch_bounds__(256) void attn_mma3()
{
    extern __shared__ __half smh[];
    __half* Qs  = smh;                     // [128][72]
    __half* Ks  = smh + 128*PQH;           // [64][72]  K[t][d]
    __half* Vts = smh + 192*PQH;           // [64][72]  Vt[d][t]
    __half* Ps  = smh + 256*PQH;           // [128][72] P[m][t]

    const int s0 = blockIdx.x * 128;
    const int bh = blockIdx.y;
    const int tid = threadIdx.x;
    const int lane = tid & 31, w = tid >> 5;
    const int qr = lane >> 2, lc = lane & 3;
    const int rowb = 16*w + qr;

    const __half* qp  = g_qh  + (size_t)bh*SS*DH;
    const __half* kp  = g_kh  + (size_t)bh*SS*DH;
    const __half* vtp = g_vth + (size_t)bh*DH*SS;

    #pragma unroll
    for (int r = 0; r < 4; r++) {
        int idx = tid + r*256, m = idx >> 3, q = (idx & 7)*8;
        *(uint4*)&Qs[m*PQH + q] = *(const uint4*)(qp + (size_t)(s0 + m)*DH + q);
    }

    float mx0 = -1e30f, mx1 = -1e30f, l0 = 0.f, l1 = 0.f;
    float o[8][4] = {};

    for (int t0 = 0; t0 < SS; t0 += 64) {
        #pragma unroll
        for (int r = 0; r < 2; r++) {
            int idx = tid + r*256, a = idx >> 3, q = (idx & 7)*8;
            *(uint4*)&Ks [a*PQH + q] = *(const uint4*)(kp  + (size_t)(t0 + a)*DH + q);
            *(uint4*)&Vts[a*PQH + q] = *(const uint4*)(vtp + (size_t)a*SS + t0 + q);
        }
        __syncthreads();

        // S = Q K^T   (4 k-chunks of 16 over d)
        float s[8][4] = {};
        #pragma unroll
        for (int ks = 0; ks < 4; ks++) {
            const int kk = 16*ks + 2*lc;
            const __half* ap = Qs + rowb*PQH + kk;
            unsigned a[4] = { fuh(ap), fuh(ap + 8*PQH), fuh(ap + 8), fuh(ap + 8*PQH + 8) };
            #pragma unroll
            for (int na = 0; na < 8; na++) {
                const __half* bp = Ks + (8*na + qr)*PQH + kk;
                unsigned b[2] = { fuh(bp), fuh(bp + 8) };
                mma16(s[na], a, b);
            }
        }

        // online softmax (rows rowb, rowb+8; lanes lc 0..3 share a row)
        float rm0 = -1e30f, rm1 = -1e30f;
        #pragma unroll
        for (int na = 0; na < 8; na++) {
            rm0 = fmaxf(rm0, fmaxf(s[na][0], s[na][1]));
            rm1 = fmaxf(rm1, fmaxf(s[na][2], s[na][3]));
        }
        #pragma unroll
        for (int msk = 1; msk <= 2; msk <<= 1) {
            rm0 = fmaxf(rm0, __shfl_xor_sync(0xffffffffu, rm0, msk));
            rm1 = fmaxf(rm1, __shfl_xor_sync(0xffffffffu, rm1, msk));
        }
        float mn0 = fmaxf(mx0, rm0), mn1 = fmaxf(mx1, rm1);
        float a0 = __expf(mx0 - mn0), a1 = __expf(mx1 - mn1);
        mx0 = mn0; mx1 = mn1;
        float rs0 = 0.f, rs1 = 0.f;
        #pragma unroll
        for (int na = 0; na < 8; na++) {
            s[na][0] = __expf(s[na][0] - mn0); rs0 += s[na][0];
            s[na][1] = __expf(s[na][1] - mn0); rs0 += s[na][1];
            s[na][2] = __expf(s[na][2] - mn1); rs1 += s[na][2];
            s[na][3] = __expf(s[na][3] - mn1); rs1 += s[na][3];
        }
        #pragma unroll
        for (int msk = 1; msk <= 2; msk <<= 1) {
            rs0 += __shfl_xor_sync(0xffffffffu, rs0, msk);
            rs1 += __shfl_xor_sync(0xffffffffu, rs1, msk);
        }
        l0 = l0*a0 + rs0;  l1 = l1*a1 + rs1;
        #pragma unroll
        for (int na = 0; na < 8; na++) {
            o[na][0] *= a0; o[na][1] *= a0; o[na][2] *= a1; o[na][3] *= a1;
            *(__half2*)&Ps[rowb*PQH + 8*na + 2*lc]     = __floats2half2_rn(s[na][0], s[na][1]);
            *(__half2*)&Ps[(rowb+8)*PQH + 8*na + 2*lc] = __floats2half2_rn(s[na][2], s[na][3]);
        }
        __syncwarp();

        // O += P V  (4 k-chunks of 16 over t)
        #pragma unroll
        for (int ks = 0; ks < 4; ks++) {
            const int kk = 16*ks + 2*lc;
            const __half* ap = Ps + rowb*PQH + kk;
            unsigned a[4] = { fuh(ap), fuh(ap + 8*PQH), fuh(ap + 8), fuh(ap + 8*PQH + 8) };
            #pragma unroll
            for (int na = 0; na < 8; na++) {
                const __half* bp = Vts + (8*na + qr)*PQH + kk;
                unsigned b[2] = { fuh(bp), fuh(bp + 8) };
                mma16(o[na], a, b);
            }
        }
        __syncthreads();
    }

    const float inv0 = 1.0f / l0, inv1 = 1.0f / l1;
    const int bb = bh >> 4, h = bh & 15;
    #pragma unroll
    for (int na = 0; na < 8; na++) {
        const int col = h*DH + 8*na + 2*lc;
        __half* p0 = g_zh + ((size_t)bb*SS + s0 + rowb) * (HH*DH) + col;
        __half* p1 = g_zh + ((size_t)bb*SS + s0 + rowb + 8) * (HH*DH) + col;
        *(__half2*)p0 = __floats2half2_rn(o[na][0]*inv0, o[na][1]*inv0);
        *(__half2*)p1 = __floats2half2_rn(o[na][2]*inv1, o[na][3]*inv1);
    }
}

// ---------------------------------------------------------------------------
// Kernel 3: output projection. grid (64, 8). out = g_zh @ Wo + bo (fp32 out).
// ---------------------------------------------------------------------------
__global__ __launch_bounds__(256) void oproj_mma3(
    const float* __restrict__ bo, float* __restrict__ out)
{
    __shared__ __half As[2*ASZH];
    __shared__ __half Bs[2*BSZH];

    const int m0 = blockIdx.x * 128;
    const int n0 = blockIdx.y * 128;

    const int tid = threadIdx.x;
    const int lane = tid & 31, wid = tid >> 5;
    const int qr = lane >> 2, lc = lane & 3;
    const int wm = (wid >> 2) * 64, wn = (wid & 3) * 32;

    const int a_row = tid >> 2,  a_q = (tid & 3) * 8;
    const int a_row2 = (tid + 256) >> 2, a_q2 = ((tid + 256) & 3) * 8;
    const int b_k2a = tid >> 5,  b_pa = tid & 31;
    const int b_k2b = (tid + 256) >> 5, b_pb = (tid + 256) & 31;

    const __half* asrc0 = g_zh + (size_t)(m0 + a_row )*EE + a_q;
    const __half* asrc1 = g_zh + (size_t)(m0 + a_row2)*EE + a_q2;
    const __half* bsrc0 = g_woh + (size_t)b_k2a*(2*EE) + n0*2 + b_pa*8;
    const __half* bsrc1 = g_woh + (size_t)b_k2b*(2*EE) + n0*2 + b_pb*8;

    const unsigned sA = (unsigned)__cvta_generic_to_shared(As);
    const unsigned sB = (unsigned)__cvta_generic_to_shared(Bs);
    const unsigned dA0 = sA + (a_row *PAH + a_q )*2;
    const unsigned dA1 = sA + (a_row2*PAH + a_q2)*2;
    const unsigned dB0 = sB + (b_k2a*PBH + b_pa*8)*2;
    const unsigned dB1 = sB + (b_k2b*PBH + b_pb*8)*2;

    float acc[4][4][4] = {};

    cpa16(dA0, asrc0); cpa16(dA1, asrc1);
    cpa16(dB0, bsrc0); cpa16(dB1, bsrc1);
    cpa_commit();

    for (int kt = 0; kt < EE/32; kt++) {
        const int st = kt & 1;
        if (kt + 1 < EE/32) {
            const int sn = (kt + 1) & 1;
            cpa16(dA0 + sn*ASZH*2, asrc0 + (kt+1)*32);
            cpa16(dA1 + sn*ASZH*2, asrc1 + (kt+1)*32);
            cpa16(dB0 + sn*BSZH*2, bsrc0 + (size_t)(kt+1)*16*(2*EE));
            cpa16(dB1 + sn*BSZH*2, bsrc1 + (size_t)(kt+1)*16*(2*EE));
            cpa_commit();
            asm volatile("cp.async.wait_group 1;\n");
        } else {
            asm volatile("cp.async.wait_group 0;\n");
        }
        __syncthreads();
        GEMM_COMPUTE16(As + st*ASZH, Bs + st*BSZH)
        __syncthreads();
    }

    #pragma unroll
    for (int ma = 0; ma < 4; ma++) {
        const int r0 = m0 + wm + 16*ma + qr;
        #pragma unroll
        for (int na = 0; na < 4; na++) {
            const int col = n0 + wn + 8*na + 2*lc;
            const float b0 = bo[col], b1 = bo[col + 1];
            *(float2*)(out + (size_t)r0*EE + col) =
                make_float2(acc[ma][na][0] + b0, acc[ma][na][1] + b1);
            *(float2*)(out + (size_t)(r0 + 8)*EE + col) =
                make_float2(acc[ma][na][2] + b0, acc[ma][na][3] + b1);
        }
    }
}

// ---------------------------------------------------------------------------
extern "C" void kernel_launch(void* const* d_in, const int* in_sizes, int n_in,
                              void* d_out, int out_size)
{
    const float* x  = (const float*)d_in[0];
    const float* Wq = (const float*)d_in[1];
    const float* bq = (const float*)d_in[2];
    const float* Wk = (const float*)d_in[3];
    const float* bk = (const float*)d_in[4];
    const float* Wv = (const float*)d_in[5];
    const float* bv = (const float*)d_in[6];
    const float* Wo = (const float*)d_in[7];
    const float* bo = (const float*)d_in[8];
    float* out = (float*)d_out;

    prep_kernel<<<12288, 256>>>(x, Wq, Wk, Wv, Wo);

    qkv_mma3<<<dim3(MM/128, 24), 256>>>(bq, bk, bv);

    const int smem = 384 * PQH * (int)sizeof(__half);   // 55296 B
    cudaFuncSetAttribute(attn_mma3, cudaFuncAttributeMaxDynamicSharedMemorySize, smem);
    attn_mma3<<<dim3(SS/128, BB*HH), 256, smem>>>();

    oproj_mma3<<<dim3(MM/128, EE/128), 256>>>(bo, out);
}

// round 9
// speedup vs baseline: 6.2792x; 1.0364x over previous
#include <cuda_runtime.h>
#include <cuda_fp16.h>
#include <math.h>

#define BB 4
#define SS 2048
#define EE 1024
#define HH 16
#define DH 64
#define MM (BB*SS)        // 8192

// ---------------------------------------------------------------------------
// Scratch (allocation-free rule: __device__ globals), all fp16
// ---------------------------------------------------------------------------
__device__ __align__(256) __half g_xh [(size_t)MM*EE];        // x, [m][e]
__device__ __align__(256) __half g_wt [(size_t)3*HH*DH*EE];   // W^T: [mat][h*64+d][e], Wq pre-scaled
__device__ __align__(256) __half g_wot[(size_t)EE*EE];        // Wo^T: [n][k]
__device__ __align__(256) __half g_qh [(size_t)BB*HH*SS*DH];  // [bh][s][d], pre-scaled
__device__ __align__(256) __half g_kh [(size_t)BB*HH*SS*DH];  // [bh][s][d]
__device__ __align__(256) __half g_vth[(size_t)BB*HH*DH*SS];  // [bh][d][s]
__device__ __align__(256) __half g_zh [(size_t)BB*SS*HH*DH];  // [b][s][h*64+d]

__device__ __forceinline__ void mma16(float* c, const unsigned* a, const unsigned* b) {
    asm volatile(
        "mma.sync.aligned.m16n8k16.row.col.f32.f16.f16.f32 "
        "{%0,%1,%2,%3},{%4,%5,%6,%7},{%8,%9},{%0,%1,%2,%3};\n"
        : "+f"(c[0]), "+f"(c[1]), "+f"(c[2]), "+f"(c[3])
        : "r"(a[0]), "r"(a[1]), "r"(a[2]), "r"(a[3]), "r"(b[0]), "r"(b[1]));
}
__device__ __forceinline__ void ldsm4(unsigned* r, unsigned addr) {
    asm volatile("ldmatrix.sync.aligned.m8n8.x4.shared.b16 {%0,%1,%2,%3}, [%4];"
                 : "=r"(r[0]), "=r"(r[1]), "=r"(r[2]), "=r"(r[3]) : "r"(addr));
}
__device__ __forceinline__ void cpa16(unsigned dst, const void* src) {
    asm volatile("cp.async.cg.shared.global [%0], [%1], 16;\n" :: "r"(dst), "l"(src));
}
__device__ __forceinline__ void cpa_commit() { asm volatile("cp.async.commit_group;\n"); }

// ---------------------------------------------------------------------------
// Kernel 0: fp16 conversion. x natural; weights transposed [n][k].
// grid 12288 x 256, 4 elements/thread.
// ---------------------------------------------------------------------------
__global__ __launch_bounds__(256) void prep_kernel(
    const float* __restrict__ x,  const float* __restrict__ Wq,
    const float* __restrict__ Wk, const float* __restrict__ Wv,
    const float* __restrict__ Wo)
{
    const size_t XN = (size_t)MM*EE;          // 8388608
    const size_t W1 = (size_t)HH*EE*DH;       // 1048576
    size_t i = ((size_t)blockIdx.x * 256 + threadIdx.x) * 4;

    if (i < XN) {
        float4 v = *(const float4*)(x + i);
        *(__half2*)(g_xh + i)     = __floats2half2_rn(v.x, v.y);
        *(__half2*)(g_xh + i + 2) = __floats2half2_rn(v.z, v.w);
    } else if (i < XN + 3*W1) {
        size_t j = i - XN;
        int mat = (int)(j / W1);
        size_t r = j - (size_t)mat * W1;
        int hd = (int)(r >> 10);             // output row (h*64+d)
        int e0 = (int)(r & 1023);            // 4 consecutive e
        int h = hd >> 6, d = hd & 63;
        const float* s = ((mat == 0) ? Wq : (mat == 1) ? Wk : Wv)
                         + ((size_t)h*EE + e0)*DH + d;
        float sc = (mat == 0) ? 0.125f : 1.0f;
        __half* dst = g_wt + (size_t)mat*W1 + (size_t)hd*EE + e0;
        *(__half2*)dst       = __floats2half2_rn(s[0]*sc,    s[DH]*sc);
        *(__half2*)(dst + 2) = __floats2half2_rn(s[2*DH]*sc, s[3*DH]*sc);
    } else {
        size_t j = i - XN - 3*W1;
        int n = (int)(j >> 10), k0 = (int)(j & 1023);
        const float* s = Wo + (size_t)k0*EE + n;
        __half* dst = g_wot + (size_t)n*EE + k0;
        *(__half2*)dst       = __floats2half2_rn(s[0],    s[EE]);
        *(__half2*)(dst + 2) = __floats2half2_rn(s[2*EE], s[3*EE]);
    }
}

// ---------------------------------------------------------------------------
// GEMM: block 128x128, 8 warps (2M x 4N), warp 64x32, K-step 32 halves,
// 3-stage cp.async. A smem [m][k] pitch 40; B^T smem [n][k] pitch 40.
// All fragments via ldmatrix.x4.
// ---------------------------------------------------------------------------
#define PT 40
#define TSZ (128*PT)         // halves per (A or B) stage
#define STG (2*TSZ)          // halves per full stage
#define NSTG 3
#define GEMM_SMEM (NSTG*STG*2)   // bytes = 61440

#define GEMM_LDSM(aB, bB)                                                      \
    _Pragma("unroll")                                                          \
    for (int ks = 0; ks < 2; ks++) {                                           \
        const int kk2 = 16*ks*2;                                               \
        unsigned af[4][4], bf[2][4];                                           \
        _Pragma("unroll")                                                      \
        for (int ma = 0; ma < 4; ma++)                                         \
            ldsm4(af[ma], (aB) + (wm + 16*ma)*(PT*2) + kk2 + aoff);            \
        _Pragma("unroll")                                                      \
        for (int nb = 0; nb < 2; nb++)                                         \
            ldsm4(bf[nb], (bB) + (wn + 16*nb)*(PT*2) + kk2 + boff);            \
        _Pragma("unroll")                                                      \
        for (int nb = 0; nb < 2; nb++)                                         \
            _Pragma("unroll")                                                  \
            for (int ma = 0; ma < 4; ma++) {                                   \
                mma16(acc[ma][2*nb],     af[ma], &bf[nb][0]);                  \
                mma16(acc[ma][2*nb + 1], af[ma], &bf[nb][2]);                  \
            }                                                                  \
    }

// frag-pointer lane offsets (bytes), computed per thread
#define FRAG_OFFSETS                                                           \
    const int laneRow = lane & 15, laneK8 = (lane >> 4) * 8;                   \
    const int laneN   = (lane & 7) + ((lane >> 4) << 3);                       \
    const int laneKb  = ((lane >> 3) & 1) * 8;                                 \
    const int aoff = (laneRow*PT + laneK8)*2;                                  \
    const int boff = (laneN  *PT + laneKb)*2;

// ---------------------------------------------------------------------------
// Kernel 1: QKV projections. grid (64, 24): y -> (mat=y>>3, head-pair=y&7).
// ---------------------------------------------------------------------------
__global__ __launch_bounds__(256) void qkv_mma4(
    const float* __restrict__ bq, const float* __restrict__ bk,
    const float* __restrict__ bv)
{
    extern __shared__ __half smg[];

    const int m0  = blockIdx.x * 128;
    const int mat = blockIdx.y >> 3;
    const int hp  = blockIdx.y & 7;

    const int tid = threadIdx.x;
    const int lane = tid & 31, wid = tid >> 5;
    const int qr = lane >> 2, lc = lane & 3;
    const int wm = (wid >> 2) * 64, wn = (wid & 3) * 32;
    FRAG_OFFSETS

    // loaders: 512 chunks of 16B per (A|B) stage -> 2 each per thread
    const int r0c = tid >> 2,        c0 = (tid & 3) * 8;
    const int r1c = (tid + 256) >> 2, c1 = ((tid + 256) & 3) * 8;

    const __half* asrc0 = g_xh + (size_t)(m0 + r0c)*EE + c0;
    const __half* asrc1 = g_xh + (size_t)(m0 + r1c)*EE + c1;
    const __half* wplane = g_wt + (size_t)mat*(HH*EE*DH) + (size_t)(hp*128)*EE;
    const __half* bsrc0 = wplane + (size_t)r0c*EE + c0;
    const __half* bsrc1 = wplane + (size_t)r1c*EE + c1;

    const unsigned sB = (unsigned)__cvta_generic_to_shared(smg);
    const unsigned dA0 = sB + (r0c*PT + c0)*2;
    const unsigned dA1 = sB + (r1c*PT + c1)*2;
    const unsigned dB0 = sB + TSZ*2 + (r0c*PT + c0)*2;
    const unsigned dB1 = sB + TSZ*2 + (r1c*PT + c1)*2;

    float acc[4][4][4] = {};

    #pragma unroll
    for (int p = 0; p < 2; p++) {   // prologue stages 0,1
        cpa16(dA0 + p*STG*2, asrc0 + p*32); cpa16(dA1 + p*STG*2, asrc1 + p*32);
        cpa16(dB0 + p*STG*2, bsrc0 + p*32); cpa16(dB1 + p*STG*2, bsrc1 + p*32);
        cpa_commit();
    }

    const int NT = EE/32;
    for (int kt = 0; kt < NT; kt++) {
        if (kt + 2 < NT) {
            const int sl = (kt + 2) % NSTG;
            cpa16(dA0 + sl*STG*2, asrc0 + (kt+2)*32); cpa16(dA1 + sl*STG*2, asrc1 + (kt+2)*32);
            cpa16(dB0 + sl*STG*2, bsrc0 + (kt+2)*32); cpa16(dB1 + sl*STG*2, bsrc1 + (kt+2)*32);
            cpa_commit();
            asm volatile("cp.async.wait_group 2;\n");
        } else if (kt + 1 < NT) {
            asm volatile("cp.async.wait_group 1;\n");
        } else {
            asm volatile("cp.async.wait_group 0;\n");
        }
        __syncthreads();
        const unsigned aB = sB + (kt % NSTG)*STG*2;
        const unsigned bB = aB + TSZ*2;
        GEMM_LDSM(aB, bB)
        __syncthreads();
    }

    const int bb = m0 >> 11;
    const float* biasm = (mat == 0) ? bq : (mat == 1) ? bk : bv;
    const float bsc = (mat == 0) ? 0.125f : 1.0f;

    #pragma unroll
    for (int ma = 0; ma < 4; ma++) {
        const int r0 = m0 + wm + 16*ma + qr;
        const int s  = r0 & (SS - 1);
        #pragma unroll
        for (int na = 0; na < 4; na++) {
            const int col = wn + 8*na + 2*lc;          // 0..126 even
            const int hs = col >> 6, d = col & 63;
            const int bh = bb*HH + 2*hp + hs;
            const float* bp = biasm + (2*hp + hs)*DH;
            const float b0 = bsc * bp[d], b1 = bsc * bp[d+1];
            if (mat < 2) {
                __half* g = (mat == 0) ? g_qh : g_kh;
                *(__half2*)(g + ((size_t)bh*SS + s    )*DH + d) =
                    __floats2half2_rn(acc[ma][na][0] + b0, acc[ma][na][1] + b1);
                *(__half2*)(g + ((size_t)bh*SS + s + 8)*DH + d) =
                    __floats2half2_rn(acc[ma][na][2] + b0, acc[ma][na][3] + b1);
            } else {
                __half* base = g_vth + (size_t)bh*DH*SS;
                base[(size_t)(d    )*SS + s    ] = __float2half_rn(acc[ma][na][0] + b0);
                base[(size_t)(d + 1)*SS + s    ] = __float2half_rn(acc[ma][na][1] + b1);
                base[(size_t)(d    )*SS + s + 8] = __float2half_rn(acc[ma][na][2] + b0);
                base[(size_t)(d + 1)*SS + s + 8] = __float2half_rn(acc[ma][na][3] + b1);
            }
        }
    }
}

// ---------------------------------------------------------------------------
// Kernel 2: flash attention, ldmatrix + cp.async double-buffered K/V.
// grid (SS/128, B*H), block 256. smem: Q | K[2] | V[2] | P, pitch 72.
// ---------------------------------------------------------------------------
#define PQH 72
#define ATT_SMEM (512*PQH*2)    // 73728 B
__global__ __launch_bounds__(256) void attn_mma4()
{
    extern __shared__ __half smh[];
    const unsigned sBase = (unsigned)__cvta_generic_to_shared(smh);
    const unsigned sQ = sBase;
    const unsigned sK = sBase + 128*PQH*2;     // 2 stages of 64 rows
    const unsigned sV = sBase + 256*PQH*2;     // 2 stages of 64 rows
    const unsigned sP = sBase + 384*PQH*2;

    const int s0 = blockIdx.x * 128;
    const int bh = blockIdx.y;
    const int tid = threadIdx.x;
    const int lane = tid & 31, w = tid >> 5;
    const int qr = lane >> 2, lc = lane & 3;
    const int rowb = 16*w + qr;

    const int laneRow = lane & 15, laneK8 = (lane >> 4) * 8;
    const int laneN   = (lane & 7) + ((lane >> 4) << 3);
    const int laneKb  = ((lane >> 3) & 1) * 8;
    const int aoff = (laneRow*PQH + laneK8)*2;
    const int boff = (laneN  *PQH + laneKb)*2;

    const __half* qp  = g_qh  + (size_t)bh*SS*DH;
    const __half* kp  = g_kh  + (size_t)bh*SS*DH;
    const __half* vtp = g_vth + (size_t)bh*DH*SS;

    // async Q load: 1024 chunks of 16B
    #pragma unroll
    for (int r = 0; r < 4; r++) {
        int idx = tid + r*256, m = idx >> 3, c = (idx & 7)*8;
        cpa16(sQ + (m*PQH + c)*2, qp + (size_t)(s0 + m)*DH + c);
    }
    cpa_commit();

    // K/V tile loader: 512 chunks each -> 2/thread (row = d or t, c along fast dim)
    const int kv_r0 = tid >> 3,         kv_c0 = (tid & 7)*8;
    const int kv_r1 = (tid + 256) >> 3, kv_c1 = ((tid + 256) & 7)*8;

    // prologue: tile 0 into stage 0
    cpa16(sK + (kv_r0*PQH + kv_c0)*2, kp  + (size_t)kv_r0*DH + kv_c0);
    cpa16(sK + (kv_r1*PQH + kv_c1)*2, kp  + (size_t)kv_r1*DH + kv_c1);
    cpa16(sV + (kv_r0*PQH + kv_c0)*2, vtp + (size_t)kv_r0*SS + kv_c0);
    cpa16(sV + (kv_r1*PQH + kv_c1)*2, vtp + (size_t)kv_r1*SS + kv_c1);
    cpa_commit();

    float mx0 = -1e30f, mx1 = -1e30f, l0 = 0.f, l1 = 0.f;
    float o[8][4] = {};

    for (int it = 0; it < SS/64; it++) {
        if (it + 1 < SS/64) {
            const int t1 = (it + 1) * 64;
            const unsigned st = ((it + 1) & 1) * 64*PQH*2;
            cpa16(sK + st + (kv_r0*PQH + kv_c0)*2, kp  + (size_t)(t1 + kv_r0)*DH + kv_c0);
            cpa16(sK + st + (kv_r1*PQH + kv_c1)*2, kp  + (size_t)(t1 + kv_r1)*DH + kv_c1);
            cpa16(sV + st + (kv_r0*PQH + kv_c0)*2, vtp + (size_t)kv_r0*SS + t1 + kv_c0);
            cpa16(sV + st + (kv_r1*PQH + kv_c1)*2, vtp + (size_t)kv_r1*SS + t1 + kv_c1);
            cpa_commit();
            asm volatile("cp.async.wait_group 1;\n");
        } else {
            asm volatile("cp.async.wait_group 0;\n");
        }
        __syncthreads();

        const unsigned stK = sK + (it & 1) * 64*PQH*2;
        const unsigned stV = sV + (it & 1) * 64*PQH*2;

        // S = Q K^T
        float s[8][4] = {};
        #pragma unroll
        for (int ks = 0; ks < 4; ks++) {
            const int kk2 = 16*ks*2;
            unsigned a[4], bf[4][4];
            ldsm4(a, sQ + (16*w)*(PQH*2) + kk2 + aoff);
            #pragma unroll
            for (int nb = 0; nb < 4; nb++)
                ldsm4(bf[nb], stK + (16*nb)*(PQH*2) + kk2 + boff);
            #pragma unroll
            for (int nb = 0; nb < 4; nb++) {
                mma16(s[2*nb],     a, &bf[nb][0]);
                mma16(s[2*nb + 1], a, &bf[nb][2]);
            }
        }

        // online softmax (rows rowb, rowb+8; lanes lc 0..3 share a row)
        float rm0 = -1e30f, rm1 = -1e30f;
        #pragma unroll
        for (int na = 0; na < 8; na++) {
            rm0 = fmaxf(rm0, fmaxf(s[na][0], s[na][1]));
            rm1 = fmaxf(rm1, fmaxf(s[na][2], s[na][3]));
        }
        #pragma unroll
        for (int msk = 1; msk <= 2; msk <<= 1) {
            rm0 = fmaxf(rm0, __shfl_xor_sync(0xffffffffu, rm0, msk));
            rm1 = fmaxf(rm1, __shfl_xor_sync(0xffffffffu, rm1, msk));
        }
        float mn0 = fmaxf(mx0, rm0), mn1 = fmaxf(mx1, rm1);
        float a0 = __expf(mx0 - mn0), a1 = __expf(mx1 - mn1);
        mx0 = mn0; mx1 = mn1;
        float rs0 = 0.f, rs1 = 0.f;
        #pragma unroll
        for (int na = 0; na < 8; na++) {
            s[na][0] = __expf(s[na][0] - mn0); rs0 += s[na][0];
            s[na][1] = __expf(s[na][1] - mn0); rs0 += s[na][1];
            s[na][2] = __expf(s[na][2] - mn1); rs1 += s[na][2];
            s[na][3] = __expf(s[na][3] - mn1); rs1 += s[na][3];
        }
        #pragma unroll
        for (int msk = 1; msk <= 2; msk <<= 1) {
            rs0 += __shfl_xor_sync(0xffffffffu, rs0, msk);
            rs1 += __shfl_xor_sync(0xffffffffu, rs1, msk);
        }
        l0 = l0*a0 + rs0;  l1 = l1*a1 + rs1;

        __half* Ph = smh + 384*PQH;
        #pragma unroll
        for (int na = 0; na < 8; na++) {
            o[na][0] *= a0; o[na][1] *= a0; o[na][2] *= a1; o[na][3] *= a1;
            *(__half2*)&Ph[rowb*PQH + 8*na + 2*lc]     = __floats2half2_rn(s[na][0], s[na][1]);
            *(__half2*)&Ph[(rowb+8)*PQH + 8*na + 2*lc] = __floats2half2_rn(s[na][2], s[na][3]);
        }
        __syncwarp();

        // O += P V
        #pragma unroll
        for (int ks = 0; ks < 4; ks++) {
            const int kk2 = 16*ks*2;
            unsigned a[4], bf[4][4];
            ldsm4(a, sP + (16*w)*(PQH*2) + kk2 + aoff);
            #pragma unroll
            for (int nb = 0; nb < 4; nb++)
                ldsm4(bf[nb], stV + (16*nb)*(PQH*2) + kk2 + boff);
            #pragma unroll
            for (int nb = 0; nb < 4; nb++) {
                mma16(o[2*nb],     a, &bf[nb][0]);
                mma16(o[2*nb + 1], a, &bf[nb][2]);
            }
        }
        __syncthreads();
    }

    const float inv0 = 1.0f / l0, inv1 = 1.0f / l1;
    const int bb = bh >> 4, h = bh & 15;
    #pragma unroll
    for (int na = 0; na < 8; na++) {
        const int col = h*DH + 8*na + 2*lc;
        __half* p0 = g_zh + ((size_t)bb*SS + s0 + rowb) * (HH*DH) + col;
        __half* p1 = g_zh + ((size_t)bb*SS + s0 + rowb + 8) * (HH*DH) + col;
        *(__half2*)p0 = __floats2half2_rn(o[na][0]*inv0, o[na][1]*inv0);
        *(__half2*)p1 = __floats2half2_rn(o[na][2]*inv1, o[na][3]*inv1);
    }
}

// ---------------------------------------------------------------------------
// Kernel 3: output projection. grid (64, 8). out = g_zh @ Wo + bo (fp32 out).
// ---------------------------------------------------------------------------
__global__ __launch_bounds__(256) void oproj_mma4(
    const float* __restrict__ bo, float* __restrict__ out)
{
    extern __shared__ __half smg[];

    const int m0 = blockIdx.x * 128;
    const int n0 = blockIdx.y * 128;

    const int tid = threadIdx.x;
    const int lane = tid & 31, wid = tid >> 5;
    const int qr = lane >> 2, lc = lane & 3;
    const int wm = (wid >> 2) * 64, wn = (wid & 3) * 32;
    FRAG_OFFSETS

    const int r0c = tid >> 2,         c0 = (tid & 3) * 8;
    const int r1c = (tid + 256) >> 2, c1 = ((tid + 256) & 3) * 8;

    const __half* asrc0 = g_zh + (size_t)(m0 + r0c)*EE + c0;
    const __half* asrc1 = g_zh + (size_t)(m0 + r1c)*EE + c1;
    const __half* bsrc0 = g_wot + (size_t)(n0 + r0c)*EE + c0;
    const __half* bsrc1 = g_wot + (size_t)(n0 + r1c)*EE + c1;

    const unsigned sB = (unsigned)__cvta_generic_to_shared(smg);
    const unsigned dA0 = sB + (r0c*PT + c0)*2;
    const unsigned dA1 = sB + (r1c*PT + c1)*2;
    const unsigned dB0 = sB + TSZ*2 + (r0c*PT + c0)*2;
    const unsigned dB1 = sB + TSZ*2 + (r1c*PT + c1)*2;

    float acc[4][4][4] = {};

    #pragma unroll
    for (int p = 0; p < 2; p++) {
        cpa16(dA0 + p*STG*2, asrc0 + p*32); cpa16(dA1 + p*STG*2, asrc1 + p*32);
        cpa16(dB0 + p*STG*2, bsrc0 + p*32); cpa16(dB1 + p*STG*2, bsrc1 + p*32);
        cpa_commit();
    }

    const int NT = EE/32;
    for (int kt = 0; kt < NT; kt++) {
        if (kt + 2 < NT) {
            const int sl = (kt + 2) % NSTG;
            cpa16(dA0 + sl*STG*2, asrc0 + (kt+2)*32); cpa16(dA1 + sl*STG*2, asrc1 + (kt+2)*32);
            cpa16(dB0 + sl*STG*2, bsrc0 + (kt+2)*32); cpa16(dB1 + sl*STG*2, bsrc1 + (kt+2)*32);
            cpa_commit();
            asm volatile("cp.async.wait_group 2;\n");
        } else if (kt + 1 < NT) {
            asm volatile("cp.async.wait_group 1;\n");
        } else {
            asm volatile("cp.async.wait_group 0;\n");
        }
        __syncthreads();
        const unsigned aB = sB + (kt % NSTG)*STG*2;
        const unsigned bB = aB + TSZ*2;
        GEMM_LDSM(aB, bB)
        __syncthreads();
    }

    #pragma unroll
    for (int ma = 0; ma < 4; ma++) {
        const int r0 = m0 + wm + 16*ma + qr;
        #pragma unroll
        for (int na = 0; na < 4; na++) {
            const int col = n0 + wn + 8*na + 2*lc;
            const float b0 = bo[col], b1 = bo[col + 1];
            *(float2*)(out + (size_t)r0*EE + col) =
                make_float2(acc[ma][na][0] + b0, acc[ma][na][1] + b1);
            *(float2*)(out + (size_t)(r0 + 8)*EE + col) =
                make_float2(acc[ma][na][2] + b0, acc[ma][na][3] + b1);
        }
    }
}

// ---------------------------------------------------------------------------
extern "C" void kernel_launch(void* const* d_in, const int* in_sizes, int n_in,
                              void* d_out, int out_size)
{
    const float* x  = (const float*)d_in[0];
    const float* Wq = (const float*)d_in[1];
    const float* bq = (const float*)d_in[2];
    const float* Wk = (const float*)d_in[3];
    const float* bk = (const float*)d_in[4];
    const float* Wv = (const float*)d_in[5];
    const float* bv = (const float*)d_in[6];
    const float* Wo = (const float*)d_in[7];
    const float* bo = (const float*)d_in[8];
    float* out = (float*)d_out;

    prep_kernel<<<12288, 256>>>(x, Wq, Wk, Wv, Wo);

    cudaFuncSetAttribute(qkv_mma4, cudaFuncAttributeMaxDynamicSharedMemorySize, GEMM_SMEM);
    qkv_mma4<<<dim3(MM/128, 24), 256, GEMM_SMEM>>>(bq, bk, bv);

    cudaFuncSetAttribute(attn_mma4, cudaFuncAttributeMaxDynamicSharedMemorySize, ATT_SMEM);
    attn_mma4<<<dim3(SS/128, BB*HH), 256, ATT_SMEM>>>();

    cudaFuncSetAttribute(oproj_mma4, cudaFuncAttributeMaxDynamicSharedMemorySize, GEMM_SMEM);
    oproj_mma4<<<dim3(MM/128, EE/128), 256, GEMM_SMEM>>>(bo, out);
}

// round 16
// speedup vs baseline: 6.6405x; 1.0575x over previous
#include <cuda_runtime.h>
#include <cuda_fp16.h>
#include <stdint.h>

#define BB 4
#define SS 2048
#define EE 1024
#define HH 16
#define DH 64
#define MM (BB*SS)        // 8192

// ---------------------------------------------------------------------------
// Scratch (allocation-free rule: __device__ globals), all fp16
// ---------------------------------------------------------------------------
__device__ __align__(256) __half g_xh [(size_t)MM*EE];        // x, [m][e]
__device__ __align__(256) __half g_wt [(size_t)3*HH*DH*EE];   // W^T: [mat][h*64+d][e], Wq pre-scaled
__device__ __align__(256) __half g_wot[(size_t)EE*EE];        // Wo^T: [n][k]
__device__ __align__(256) __half g_qh [(size_t)BB*HH*SS*DH];  // [bh][s][d], pre-scaled
__device__ __align__(256) __half g_kh [(size_t)BB*HH*SS*DH];  // [bh][s][d]
__device__ __align__(256) __half g_vth[(size_t)BB*HH*DH*SS];  // [bh][d][s]
__device__ __align__(256) __half g_zh [(size_t)BB*SS*HH*DH];  // [b][s][h*64+d]

__device__ __forceinline__ void mma16(float* c, const unsigned* a, const unsigned* b) {
    asm volatile(
        "mma.sync.aligned.m16n8k16.row.col.f32.f16.f16.f32 "
        "{%0,%1,%2,%3},{%4,%5,%6,%7},{%8,%9},{%0,%1,%2,%3};\n"
        : "+f"(c[0]), "+f"(c[1]), "+f"(c[2]), "+f"(c[3])
        : "r"(a[0]), "r"(a[1]), "r"(a[2]), "r"(a[3]), "r"(b[0]), "r"(b[1]));
}
__device__ __forceinline__ void ldsm4(unsigned* r, unsigned addr) {
    asm volatile("ldmatrix.sync.aligned.m8n8.x4.shared.b16 {%0,%1,%2,%3}, [%4];"
                 : "=r"(r[0]), "=r"(r[1]), "=r"(r[2]), "=r"(r[3]) : "r"(addr));
}
__device__ __forceinline__ void cpa16(unsigned dst, const void* src) {
    asm volatile("cp.async.cg.shared.global [%0], [%1], 16;\n" :: "r"(dst), "l"(src));
}
__device__ __forceinline__ void cpa_commit() { asm volatile("cp.async.commit_group;\n"); }
__device__ __forceinline__ unsigned h2u(__half2 h) { return *(unsigned*)&h; }

// ---------------------------------------------------------------------------
// Kernel 0: fp16 conversion. x natural; weights transposed [n][k].
// ---------------------------------------------------------------------------
__global__ __launch_bounds__(256) void prep_kernel(
    const float* __restrict__ x,  const float* __restrict__ Wq,
    const float* __restrict__ Wk, const float* __restrict__ Wv,
    const float* __restrict__ Wo)
{
    const size_t XN = (size_t)MM*EE;
    const size_t W1 = (size_t)HH*EE*DH;
    size_t i = ((size_t)blockIdx.x * 256 + threadIdx.x) * 4;

    if (i < XN) {
        float4 v = *(const float4*)(x + i);
        *(__half2*)(g_xh + i)     = __floats2half2_rn(v.x, v.y);
        *(__half2*)(g_xh + i + 2) = __floats2half2_rn(v.z, v.w);
    } else if (i < XN + 3*W1) {
        size_t j = i - XN;
        int mat = (int)(j / W1);
        size_t r = j - (size_t)mat * W1;
        int hd = (int)(r >> 10);
        int e0 = (int)(r & 1023);
        int h = hd >> 6, d = hd & 63;
        const float* s = ((mat == 0) ? Wq : (mat == 1) ? Wk : Wv)
                         + ((size_t)h*EE + e0)*DH + d;
        float sc = (mat == 0) ? 0.125f : 1.0f;
        __half* dst = g_wt + (size_t)mat*W1 + (size_t)hd*EE + e0;
        *(__half2*)dst       = __floats2half2_rn(s[0]*sc,    s[DH]*sc);
        *(__half2*)(dst + 2) = __floats2half2_rn(s[2*DH]*sc, s[3*DH]*sc);
    } else {
        size_t j = i - XN - 3*W1;
        int n = (int)(j >> 10), k0 = (int)(j & 1023);
        const float* s = Wo + (size_t)k0*EE + n;
        __half* dst = g_wot + (size_t)n*EE + k0;
        *(__half2*)dst       = __floats2half2_rn(s[0],    s[EE]);
        *(__half2*)(dst + 2) = __floats2half2_rn(s[2*EE], s[3*EE]);
    }
}

// ---------------------------------------------------------------------------
// GEMM: block 128x128, 8 warps (2M x 4N), warp 64x32, K-step 32 halves,
// 3-stage cp.async. A smem [m][k] pitch 40; B^T smem [n][k] pitch 40.
// ---------------------------------------------------------------------------
#define PT 40
#define TSZ (128*PT)
#define STG (2*TSZ)
#define NSTG 3
#define GEMM_SMEM (NSTG*STG*2)   // 61440 B

#define GEMM_LDSM(aB, bB)                                                      \
    _Pragma("unroll")                                                          \
    for (int ks = 0; ks < 2; ks++) {                                           \
        const int kk2 = 16*ks*2;                                               \
        unsigned af[4][4], bf[2][4];                                           \
        _Pragma("unroll")                                                      \
        for (int ma = 0; ma < 4; ma++)                                         \
            ldsm4(af[ma], (aB) + (wm + 16*ma)*(PT*2) + kk2 + aoff);            \
        _Pragma("unroll")                                                      \
        for (int nb = 0; nb < 2; nb++)                                         \
            ldsm4(bf[nb], (bB) + (wn + 16*nb)*(PT*2) + kk2 + boff);            \
        _Pragma("unroll")                                                      \
        for (int nb = 0; nb < 2; nb++)                                         \
            _Pragma("unroll")                                                  \
            for (int ma = 0; ma < 4; ma++) {                                   \
                mma16(acc[ma][2*nb],     af[ma], &bf[nb][0]);                  \
                mma16(acc[ma][2*nb + 1], af[ma], &bf[nb][2]);                  \
            }                                                                  \
    }

#define FRAG_OFFSETS                                                           \
    const int laneRow = lane & 15, laneK8 = (lane >> 4) * 8;                   \
    const int laneN   = (lane & 7) + ((lane >> 4) << 3);                       \
    const int laneKb  = ((lane >> 3) & 1) * 8;                                 \
    const int aoff = (laneRow*PT + laneK8)*2;                                  \
    const int boff = (laneN  *PT + laneKb)*2;

// ---------------------------------------------------------------------------
// Kernel 1: QKV projections. grid (64, 24): y -> (mat=y>>3, head-pair=y&7).
// ---------------------------------------------------------------------------
__global__ __launch_bounds__(256) void qkv_mma4(
    const float* __restrict__ bq, const float* __restrict__ bk,
    const float* __restrict__ bv)
{
    extern __shared__ __half smg[];

    const int m0  = blockIdx.x * 128;
    const int mat = blockIdx.y >> 3;
    const int hp  = blockIdx.y & 7;

    const int tid = threadIdx.x;
    const int lane = tid & 31, wid = tid >> 5;
    const int qr = lane >> 2, lc = lane & 3;
    const int wm = (wid >> 2) * 64, wn = (wid & 3) * 32;
    FRAG_OFFSETS

    const int r0c = tid >> 2,        c0 = (tid & 3) * 8;
    const int r1c = (tid + 256) >> 2, c1 = ((tid + 256) & 3) * 8;

    const __half* asrc0 = g_xh + (size_t)(m0 + r0c)*EE + c0;
    const __half* asrc1 = g_xh + (size_t)(m0 + r1c)*EE + c1;
    const __half* wplane = g_wt + (size_t)mat*(HH*EE*DH) + (size_t)(hp*128)*EE;
    const __half* bsrc0 = wplane + (size_t)r0c*EE + c0;
    const __half* bsrc1 = wplane + (size_t)r1c*EE + c1;

    const unsigned sB = (unsigned)__cvta_generic_to_shared(smg);
    const unsigned dA0 = sB + (r0c*PT + c0)*2;
    const unsigned dA1 = sB + (r1c*PT + c1)*2;
    const unsigned dB0 = sB + TSZ*2 + (r0c*PT + c0)*2;
    const unsigned dB1 = sB + TSZ*2 + (r1c*PT + c1)*2;

    float acc[4][4][4] = {};

    #pragma unroll
    for (int p = 0; p < 2; p++) {
        cpa16(dA0 + p*STG*2, asrc0 + p*32); cpa16(dA1 + p*STG*2, asrc1 + p*32);
        cpa16(dB0 + p*STG*2, bsrc0 + p*32); cpa16(dB1 + p*STG*2, bsrc1 + p*32);
        cpa_commit();
    }

    const int NT = EE/32;
    for (int kt = 0; kt < NT; kt++) {
        if (kt + 2 < NT) {
            const int sl = (kt + 2) % NSTG;
            cpa16(dA0 + sl*STG*2, asrc0 + (kt+2)*32); cpa16(dA1 + sl*STG*2, asrc1 + (kt+2)*32);
            cpa16(dB0 + sl*STG*2, bsrc0 + (kt+2)*32); cpa16(dB1 + sl*STG*2, bsrc1 + (kt+2)*32);
            cpa_commit();
            asm volatile("cp.async.wait_group 2;\n");
        } else if (kt + 1 < NT) {
            asm volatile("cp.async.wait_group 1;\n");
        } else {
            asm volatile("cp.async.wait_group 0;\n");
        }
        __syncthreads();
        const unsigned aB = sB + (kt % NSTG)*STG*2;
        const unsigned bB = aB + TSZ*2;
        GEMM_LDSM(aB, bB)
        __syncthreads();
    }

    const int bb = m0 >> 11;
    const float* biasm = (mat == 0) ? bq : (mat == 1) ? bk : bv;
    const float bsc = (mat == 0) ? 0.125f : 1.0f;

    #pragma unroll
    for (int ma = 0; ma < 4; ma++) {
        const int r0 = m0 + wm + 16*ma + qr;
        const int s  = r0 & (SS - 1);
        #pragma unroll
        for (int na = 0; na < 4; na++) {
            const int col = wn + 8*na + 2*lc;
            const int hs = col >> 6, d = col & 63;
            const int bh = bb*HH + 2*hp + hs;
            const float* bp = biasm + (2*hp + hs)*DH;
            const float b0 = bsc * bp[d], b1 = bsc * bp[d+1];
            if (mat < 2) {
                __half* g = (mat == 0) ? g_qh : g_kh;
                *(__half2*)(g + ((size_t)bh*SS + s    )*DH + d) =
                    __floats2half2_rn(acc[ma][na][0] + b0, acc[ma][na][1] + b1);
                *(__half2*)(g + ((size_t)bh*SS + s + 8)*DH + d) =
                    __floats2half2_rn(acc[ma][na][2] + b0, acc[ma][na][3] + b1);
            } else {
                __half* base = g_vth + (size_t)bh*DH*SS;
                base[(size_t)(d    )*SS + s    ] = __float2half_rn(acc[ma][na][0] + b0);
                base[(size_t)(d + 1)*SS + s    ] = __float2half_rn(acc[ma][na][1] + b1);
                base[(size_t)(d    )*SS + s + 8] = __float2half_rn(acc[ma][na][2] + b0);
                base[(size_t)(d + 1)*SS + s + 8] = __float2half_rn(acc[ma][na][3] + b1);
            }
        }
    }
}

// ---------------------------------------------------------------------------
// Kernel 2: flash attention. Register-resident P (C-frag == A-frag identity),
// 3-stage cp.async K/V ring, ONE __syncthreads per key tile.
// grid (SS/128, B*H), block 256. smem = Q[128] + 3 x (K[64] | V[64]), pitch 72.
// ---------------------------------------------------------------------------
#define PQH 72
#define KVSTG (128*PQH*2)              // bytes per K+V stage
#define ATT_SMEM (128*PQH*2 + 3*KVSTG) // 73728 B
__global__ __launch_bounds__(256) void attn_mma5()
{
    extern __shared__ __half smh[];
    const unsigned sBase = (unsigned)__cvta_generic_to_shared(smh);
    const unsigned sQ  = sBase;
    const unsigned sKV = sBase + 128*PQH*2;   // stage s: K at +s*KVSTG, V at +s*KVSTG+64*PQH*2

    const int s0 = blockIdx.x * 128;
    const int bh = blockIdx.y;
    const int tid = threadIdx.x;
    const int lane = tid & 31, w = tid >> 5;
    const int qr = lane >> 2, lc = lane & 3;
    const int rowb = 16*w + qr;

    const int laneRow = lane & 15, laneK8 = (lane >> 4) * 8;
    const int laneN   = (lane & 7) + ((lane >> 4) << 3);
    const int laneKb  = ((lane >> 3) & 1) * 8;
    const int aoff = (laneRow*PQH + laneK8)*2;
    const int boff = (laneN  *PQH + laneKb)*2;

    const __half* qp  = g_qh  + (size_t)bh*SS*DH;
    const __half* kp  = g_kh  + (size_t)bh*SS*DH;
    const __half* vtp = g_vth + (size_t)bh*DH*SS;

    // K/V loader coords: 2 chunks each of K and V per thread
    const int kv_r0 = tid >> 3,         kv_c0 = (tid & 7)*8;
    const int kv_r1 = (tid + 256) >> 3, kv_c1 = ((tid + 256) & 7)*8;

    // prologue: G0 = Q + KV tile0 (stage 0); G1 = KV tile1 (stage 1)
    #pragma unroll
    for (int r = 0; r < 4; r++) {
        int idx = tid + r*256, m = idx >> 3, c = (idx & 7)*8;
        cpa16(sQ + (m*PQH + c)*2, qp + (size_t)(s0 + m)*DH + c);
    }
    {
        const unsigned sk = sKV, sv = sKV + 64*PQH*2;
        cpa16(sk + (kv_r0*PQH + kv_c0)*2, kp  + (size_t)kv_r0*DH + kv_c0);
        cpa16(sk + (kv_r1*PQH + kv_c1)*2, kp  + (size_t)kv_r1*DH + kv_c1);
        cpa16(sv + (kv_r0*PQH + kv_c0)*2, vtp + (size_t)kv_r0*SS + kv_c0);
        cpa16(sv + (kv_r1*PQH + kv_c1)*2, vtp + (size_t)kv_r1*SS + kv_c1);
        cpa_commit();
    }
    {
        const unsigned sk = sKV + KVSTG, sv = sKV + KVSTG + 64*PQH*2;
        cpa16(sk + (kv_r0*PQH + kv_c0)*2, kp  + (size_t)(64 + kv_r0)*DH + kv_c0);
        cpa16(sk + (kv_r1*PQH + kv_c1)*2, kp  + (size_t)(64 + kv_r1)*DH + kv_c1);
        cpa16(sv + (kv_r0*PQH + kv_c0)*2, vtp + (size_t)kv_r0*SS + 64 + kv_c0);
        cpa16(sv + (kv_r1*PQH + kv_c1)*2, vtp + (size_t)kv_r1*SS + 64 + kv_c1);
        cpa_commit();
    }

    float mx0 = -1e30f, mx1 = -1e30f, l0 = 0.f, l1 = 0.f;
    float o[8][4] = {};

    const int NIT = SS/64;
    for (int it = 0; it < NIT; it++) {
        if (it + 1 < NIT) asm volatile("cp.async.wait_group 1;\n");
        else              asm volatile("cp.async.wait_group 0;\n");
        __syncthreads();   // tile `it` visible to all; all warps past reads of stage (it+2)%3

        if (it + 2 < NIT) {  // prefetch tile it+2 into stage (it+2)%3
            const int t2 = (it + 2) * 64;
            const unsigned sk = sKV + (unsigned)((it + 2) % 3)*KVSTG;
            const unsigned sv = sk + 64*PQH*2;
            cpa16(sk + (kv_r0*PQH + kv_c0)*2, kp  + (size_t)(t2 + kv_r0)*DH + kv_c0);
            cpa16(sk + (kv_r1*PQH + kv_c1)*2, kp  + (size_t)(t2 + kv_r1)*DH + kv_c1);
            cpa16(sv + (kv_r0*PQH + kv_c0)*2, vtp + (size_t)kv_r0*SS + t2 + kv_c0);
            cpa16(sv + (kv_r1*PQH + kv_c1)*2, vtp + (size_t)kv_r1*SS + t2 + kv_c1);
            cpa_commit();
        }

        const unsigned stK = sKV + (unsigned)(it % 3)*KVSTG;
        const unsigned stV = stK + 64*PQH*2;

        // S = Q K^T
        float s[8][4] = {};
        #pragma unroll
        for (int ks = 0; ks < 4; ks++) {
            const int kk2 = 16*ks*2;
            unsigned a[4], bf[4][4];
            ldsm4(a, sQ + (16*w)*(PQH*2) + kk2 + aoff);
            #pragma unroll
            for (int nb = 0; nb < 4; nb++)
                ldsm4(bf[nb], stK + (16*nb)*(PQH*2) + kk2 + boff);
            #pragma unroll
            for (int nb = 0; nb < 4; nb++) {
                mma16(s[2*nb],     a, &bf[nb][0]);
                mma16(s[2*nb + 1], a, &bf[nb][2]);
            }
        }

        // online softmax (rows rowb, rowb+8; lanes lc 0..3 share a row)
        float rm0 = -1e30f, rm1 = -1e30f;
        #pragma unroll
        for (int na = 0; na < 8; na++) {
            rm0 = fmaxf(rm0, fmaxf(s[na][0], s[na][1]));
            rm1 = fmaxf(rm1, fmaxf(s[na][2], s[na][3]));
        }
        #pragma unroll
        for (int msk = 1; msk <= 2; msk <<= 1) {
            rm0 = fmaxf(rm0, __shfl_xor_sync(0xffffffffu, rm0, msk));
            rm1 = fmaxf(rm1, __shfl_xor_sync(0xffffffffu, rm1, msk));
        }
        float mn0 = fmaxf(mx0, rm0), mn1 = fmaxf(mx1, rm1);
        float a0 = __expf(mx0 - mn0), a1 = __expf(mx1 - mn1);
        mx0 = mn0; mx1 = mn1;
        float rs0 = 0.f, rs1 = 0.f;
        #pragma unroll
        for (int na = 0; na < 8; na++) {
            s[na][0] = __expf(s[na][0] - mn0); rs0 += s[na][0];
            s[na][1] = __expf(s[na][1] - mn0); rs0 += s[na][1];
            s[na][2] = __expf(s[na][2] - mn1); rs1 += s[na][2];
            s[na][3] = __expf(s[na][3] - mn1); rs1 += s[na][3];
        }
        #pragma unroll
        for (int msk = 1; msk <= 2; msk <<= 1) {
            rs0 += __shfl_xor_sync(0xffffffffu, rs0, msk);
            rs1 += __shfl_xor_sync(0xffffffffu, rs1, msk);
        }
        l0 = l0*a0 + rs0;  l1 = l1*a1 + rs1;
        #pragma unroll
        for (int na = 0; na < 8; na++) {
            o[na][0] *= a0; o[na][1] *= a0; o[na][2] *= a1; o[na][3] *= a1;
        }

        // O += P V : P stays in registers (C-frag of S == A-frag for PV)
        #pragma unroll
        for (int kc = 0; kc < 4; kc++) {
            const int kk2 = 16*kc*2;
            unsigned a[4];
            a[0] = h2u(__floats2half2_rn(s[2*kc][0],   s[2*kc][1]));
            a[1] = h2u(__floats2half2_rn(s[2*kc][2],   s[2*kc][3]));
            a[2] = h2u(__floats2half2_rn(s[2*kc+1][0], s[2*kc+1][1]));
            a[3] = h2u(__floats2half2_rn(s[2*kc+1][2], s[2*kc+1][3]));
            unsigned bf[4][4];
            #pragma unroll
            for (int nb = 0; nb < 4; nb++)
                ldsm4(bf[nb], stV + (16*nb)*(PQH*2) + kk2 + boff);
            #pragma unroll
            for (int nb = 0; nb < 4; nb++) {
                mma16(o[2*nb],     a, &bf[nb][0]);
                mma16(o[2*nb + 1], a, &bf[nb][2]);
            }
        }
    }

    const float inv0 = 1.0f / l0, inv1 = 1.0f / l1;
    const int bb = bh >> 4, h = bh & 15;
    #pragma unroll
    for (int na = 0; na < 8; na++) {
        const int col = h*DH + 8*na + 2*lc;
        __half* p0 = g_zh + ((size_t)bb*SS + s0 + rowb) * (HH*DH) + col;
        __half* p1 = g_zh + ((size_t)bb*SS + s0 + rowb + 8) * (HH*DH) + col;
        *(__half2*)p0 = __floats2half2_rn(o[na][0]*inv0, o[na][1]*inv0);
        *(__half2*)p1 = __floats2half2_rn(o[na][2]*inv1, o[na][3]*inv1);
    }
}

// ---------------------------------------------------------------------------
// Kernel 3: output projection. grid (64, 8). out = g_zh @ Wo + bo (fp32 out).
// ---------------------------------------------------------------------------
__global__ __launch_bounds__(256) void oproj_mma4(
    const float* __restrict__ bo, float* __restrict__ out)
{
    extern __shared__ __half smg[];

    const int m0 = blockIdx.x * 128;
    const int n0 = blockIdx.y * 128;

    const int tid = threadIdx.x;
    const int lane = tid & 31, wid = tid >> 5;
    const int qr = lane >> 2, lc = lane & 3;
    const int wm = (wid >> 2) * 64, wn = (wid & 3) * 32;
    FRAG_OFFSETS

    const int r0c = tid >> 2,         c0 = (tid & 3) * 8;
    const int r1c = (tid + 256) >> 2, c1 = ((tid + 256) & 3) * 8;

    const __half* asrc0 = g_zh + (size_t)(m0 + r0c)*EE + c0;
    const __half* asrc1 = g_zh + (size_t)(m0 + r1c)*EE + c1;
    const __half* bsrc0 = g_wot + (size_t)(n0 + r0c)*EE + c0;
    const __half* bsrc1 = g_wot + (size_t)(n0 + r1c)*EE + c1;

    const unsigned sB = (unsigned)__cvta_generic_to_shared(smg);
    const unsigned dA0 = sB + (r0c*PT + c0)*2;
    const unsigned dA1 = sB + (r1c*PT + c1)*2;
    const unsigned dB0 = sB + TSZ*2 + (r0c*PT + c0)*2;
    const unsigned dB1 = sB + TSZ*2 + (r1c*PT + c1)*2;

    float acc[4][4][4] = {};

    #pragma unroll
    for (int p = 0; p < 2; p++) {
        cpa16(dA0 + p*STG*2, asrc0 + p*32); cpa16(dA1 + p*STG*2, asrc1 + p*32);
        cpa16(dB0 + p*STG*2, bsrc0 + p*32); cpa16(dB1 + p*STG*2, bsrc1 + p*32);
        cpa_commit();
    }

    const int NT = EE/32;
    for (int kt = 0; kt < NT; kt++) {
        if (kt + 2 < NT) {
            const int sl = (kt + 2) % NSTG;
            cpa16(dA0 + sl*STG*2, asrc0 + (kt+2)*32); cpa16(dA1 + sl*STG*2, asrc1 + (kt+2)*32);
            cpa16(dB0 + sl*STG*2, bsrc0 + (kt+2)*32); cpa16(dB1 + sl*STG*2, bsrc1 + (kt+2)*32);
            cpa_commit();
            asm volatile("cp.async.wait_group 2;\n");
        } else if (kt + 1 < NT) {
            asm volatile("cp.async.wait_group 1;\n");
        } else {
            asm volatile("cp.async.wait_group 0;\n");
        }
        __syncthreads();
        const unsigned aB = sB + (kt % NSTG)*STG*2;
        const unsigned bB = aB + TSZ*2;
        GEMM_LDSM(aB, bB)
        __syncthreads();
    }

    #pragma unroll
    for (int ma = 0; ma < 4; ma++) {
        const int r0 = m0 + wm + 16*ma + qr;
        #pragma unroll
        for (int na = 0; na < 4; na++) {
            const int col = n0 + wn + 8*na + 2*lc;
            const float b0 = bo[col], b1 = bo[col + 1];
            *(float2*)(out + (size_t)r0*EE + col) =
                make_float2(acc[ma][na][0] + b0, acc[ma][na][1] + b1);
            *(float2*)(out + (size_t)(r0 + 8)*EE + col) =
                make_float2(acc[ma][na][2] + b0, acc[ma][na][3] + b1);
        }
    }
}

// ---------------------------------------------------------------------------
extern "C" void kernel_launch(void* const* d_in, const int* in_sizes, int n_in,
                              void* d_out, int out_size)
{
    const float* x  = (const float*)d_in[0];
    const float* Wq = (const float*)d_in[1];
    const float* bq = (const float*)d_in[2];
    const float* Wk = (const float*)d_in[3];
    const float* bk = (const float*)d_in[4];
    const float* Wv = (const float*)d_in[5];
    const float* bv = (const float*)d_in[6];
    const float* Wo = (const float*)d_in[7];
    const float* bo = (const float*)d_in[8];
    float* out = (float*)d_out;

    prep_kernel<<<12288, 256>>>(x, Wq, Wk, Wv, Wo);

    cudaFuncSetAttribute(qkv_mma4, cudaFuncAttributeMaxDynamicSharedMemorySize, GEMM_SMEM);
    qkv_mma4<<<dim3(MM/128, 24), 256, GEMM_SMEM>>>(bq, bk, bv);

    cudaFuncSetAttribute(attn_mma5, cudaFuncAttributeMaxDynamicSharedMemorySize, ATT_SMEM);
    attn_mma5<<<dim3(SS/128, BB*HH), 256, ATT_SMEM>>>();

    cudaFuncSetAttribute(oproj_mma4, cudaFuncAttributeMaxDynamicSharedMemorySize, GEMM_SMEM);
    oproj_mma4<<<dim3(MM/128, EE/128), 256, GEMM_SMEM>>>(bo, out);
}